// round 1
// baseline (speedup 1.0000x reference)
#include <cuda_runtime.h>

// Problem constants
#define BSZ   2
#define CDIM  1024
#define CIDIM 512
#define NDIM  6272     // 32*14*14, = 98 * 64
#define TDIM  32

// Scratch (allocation-free rule: __device__ globals)
__device__ __align__(256) float g_K[(size_t)BSZ * CIDIM * NDIM];
__device__ __align__(256) float g_Q[(size_t)BSZ * CIDIM * NDIM];
__device__ __align__(256) float g_V[(size_t)BSZ * CIDIM * NDIM];
__device__ __align__(256) float g_Y[(size_t)BSZ * CIDIM * NDIM];
__device__ __align__(256) float g_S[(size_t)BSZ * NDIM * NDIM];   // 315 MB attention matrix

// ---------------------------------------------------------------------------
// Tiled SGEMM: C[M,N] = scale * (A op B) + epilogue
//   TA=0: A[m*lda + k]   TA=1: A[k*lda + m]
//   TB=0: B[k*ldb + n]   TB=1: B[n*ldb + k]
//   EPI=0: + bias[m]
//   EPI=1: (scale only)
//   EPI=2: + bias[m] + resid[m*ldc + n]
// Block tile 64x64, K-tile 16, 256 threads, 4x4 per-thread microtile.
// All dims assumed multiples of tile sizes (true for this problem).
// ---------------------------------------------------------------------------
template <int TA, int TB, int EPI>
__global__ __launch_bounds__(256)
void gemm64(const float* __restrict__ Ag, const float* __restrict__ Bg,
            float* __restrict__ Cg,
            int M, int Nn, int Kd, int lda, int ldb, int ldc,
            size_t aStr, size_t bStr, size_t cStr,
            const float* __restrict__ bias,
            const float* __restrict__ resid, size_t rStr,
            float scale)
{
    const float* A = Ag + (size_t)blockIdx.z * aStr;
    const float* B = Bg + (size_t)blockIdx.z * bStr;
    float*       C = Cg + (size_t)blockIdx.z * cStr;

    __shared__ float As[16][64];
    __shared__ float Bs[16][64];

    const int tx  = threadIdx.x;           // 0..15
    const int ty  = threadIdx.y;           // 0..15
    const int tid = ty * 16 + tx;          // 0..255
    const int bm  = blockIdx.y;
    const int bn  = blockIdx.x;

    float acc[4][4] = {};

    for (int k0 = 0; k0 < Kd; k0 += 16) {
        // ---- load A tile into As[k][m] ----
        if (TA == 0) {
            const int m  = tid >> 2;              // 0..63
            const int kg = (tid & 3) * 4;         // 0,4,8,12
            float4 a4 = *(const float4*)(A + (size_t)(bm * 64 + m) * lda + k0 + kg);
            As[kg + 0][m] = a4.x; As[kg + 1][m] = a4.y;
            As[kg + 2][m] = a4.z; As[kg + 3][m] = a4.w;
        } else {
            const int kk = tid >> 4;              // 0..15
            const int mg = (tid & 15) * 4;        // 0..60
            *(float4*)(&As[kk][mg]) =
                *(const float4*)(A + (size_t)(k0 + kk) * lda + bm * 64 + mg);
        }
        // ---- load B tile into Bs[k][n] ----
        if (TB == 0) {
            const int kk = tid >> 4;
            const int ng = (tid & 15) * 4;
            *(float4*)(&Bs[kk][ng]) =
                *(const float4*)(B + (size_t)(k0 + kk) * ldb + bn * 64 + ng);
        } else {
            const int n  = tid >> 2;
            const int kg = (tid & 3) * 4;
            float4 b4 = *(const float4*)(B + (size_t)(bn * 64 + n) * ldb + k0 + kg);
            Bs[kg + 0][n] = b4.x; Bs[kg + 1][n] = b4.y;
            Bs[kg + 2][n] = b4.z; Bs[kg + 3][n] = b4.w;
        }
        __syncthreads();

        #pragma unroll
        for (int kk = 0; kk < 16; kk++) {
            float4 a = *(const float4*)(&As[kk][ty * 4]);
            float4 b = *(const float4*)(&Bs[kk][tx * 4]);
            acc[0][0] += a.x * b.x; acc[0][1] += a.x * b.y;
            acc[0][2] += a.x * b.z; acc[0][3] += a.x * b.w;
            acc[1][0] += a.y * b.x; acc[1][1] += a.y * b.y;
            acc[1][2] += a.y * b.z; acc[1][3] += a.y * b.w;
            acc[2][0] += a.z * b.x; acc[2][1] += a.z * b.y;
            acc[2][2] += a.z * b.z; acc[2][3] += a.z * b.w;
            acc[3][0] += a.w * b.x; acc[3][1] += a.w * b.y;
            acc[3][2] += a.w * b.z; acc[3][3] += a.w * b.w;
        }
        __syncthreads();
    }

    const int m0 = bm * 64 + ty * 4;
    const int n0 = bn * 64 + tx * 4;
    #pragma unroll
    for (int i = 0; i < 4; i++) {
        float bi = 0.f;
        if (EPI == 0 || EPI == 2) bi = bias[m0 + i];
        float* crow = C + (size_t)(m0 + i) * ldc;
        const float* rrow = (EPI == 2)
            ? (resid + (size_t)blockIdx.z * rStr + (size_t)(m0 + i) * ldc)
            : nullptr;
        #pragma unroll
        for (int j = 0; j < 4; j++) {
            float v = acc[i][j] * scale + bi;
            if (EPI == 2) v += rrow[n0 + j];
            crow[n0 + j] = v;
        }
    }
}

// ---------------------------------------------------------------------------
// Row softmax over last axis. One block (256 thr) per row of length n=6272.
// Single global read + single write (values held in registers).
// ---------------------------------------------------------------------------
#define SM_VPT 25   // ceil(6272/256)
__global__ __launch_bounds__(256)
void softmax_rows(float* __restrict__ a, int n)
{
    float* row = a + (size_t)blockIdx.x * n;
    const int t = threadIdx.x;
    __shared__ float red[256];

    float vals[SM_VPT];
    float mx = -3.402823466e38f;
    #pragma unroll
    for (int v = 0; v < SM_VPT; v++) {
        int j = v * 256 + t;
        if (j < n) { vals[v] = row[j]; mx = fmaxf(mx, vals[v]); }
        else vals[v] = -3.402823466e38f;
    }
    red[t] = mx; __syncthreads();
    for (int s = 128; s > 0; s >>= 1) {
        if (t < s) red[t] = fmaxf(red[t], red[t + s]);
        __syncthreads();
    }
    mx = red[0];
    __syncthreads();

    float sum = 0.f;
    #pragma unroll
    for (int v = 0; v < SM_VPT; v++) {
        int j = v * 256 + t;
        if (j < n) { vals[v] = __expf(vals[v] - mx); sum += vals[v]; }
    }
    red[t] = sum; __syncthreads();
    for (int s = 128; s > 0; s >>= 1) {
        if (t < s) red[t] += red[t + s];
        __syncthreads();
    }
    const float inv = 1.f / red[0];

    #pragma unroll
    for (int v = 0; v < SM_VPT; v++) {
        int j = v * 256 + t;
        if (j < n) row[j] = vals[v] * inv;
    }
}

// ---------------------------------------------------------------------------
extern "C" void kernel_launch(void* const* d_in, const int* in_sizes, int n_in,
                              void* d_out, int out_size)
{
    const float* x  = (const float*)d_in[0];   // (B, C, N)
    const float* Wk = (const float*)d_in[1];   // (CI, C)
    const float* bk = (const float*)d_in[2];
    const float* Wq = (const float*)d_in[3];
    const float* bq = (const float*)d_in[4];
    const float* Wv = (const float*)d_in[5];
    const float* bv = (const float*)d_in[6];
    const float* Wo = (const float*)d_in[7];   // (C, CI)
    const float* bo = (const float*)d_in[8];
    float* out = (float*)d_out;                // (B, C, N)

    float *K, *Q, *V, *Y, *S;
    cudaGetSymbolAddress((void**)&K, g_K);
    cudaGetSymbolAddress((void**)&Q, g_Q);
    cudaGetSymbolAddress((void**)&V, g_V);
    cudaGetSymbolAddress((void**)&Y, g_Y);
    cudaGetSymbolAddress((void**)&S, g_S);

    const dim3 blk(16, 16);
    const size_t pstr = (size_t)CIDIM * NDIM;        // per-batch stride of K/Q/V/Y
    const size_t xstr = (size_t)CDIM * NDIM;         // per-batch stride of x/out
    const size_t sstr = (size_t)NDIM * NDIM;         // per-batch stride of S

    // 1) Projections: P[d,n] = W[d,:] @ x[b,:,n] + b[d]   (CI x C x N)
    const dim3 gProj(NDIM / 64, CIDIM / 64, BSZ);
    gemm64<0, 0, 0><<<gProj, blk>>>(Wk, x, K, CIDIM, NDIM, CDIM,
                                    CDIM, NDIM, NDIM, 0, xstr, pstr,
                                    bk, nullptr, 0, 1.0f);
    gemm64<0, 0, 0><<<gProj, blk>>>(Wq, x, Q, CIDIM, NDIM, CDIM,
                                    CDIM, NDIM, NDIM, 0, xstr, pstr,
                                    bq, nullptr, 0, 1.0f);
    gemm64<0, 0, 0><<<gProj, blk>>>(Wv, x, V, CIDIM, NDIM, CDIM,
                                    CDIM, NDIM, NDIM, 0, xstr, pstr,
                                    bv, nullptr, 0, 1.0f);

    // 2) Scores: S[i,j] = (1/T) * sum_d K[d,i] * Q[d,j]   (N x CI x N, TN gemm)
    const dim3 gS(NDIM / 64, NDIM / 64, BSZ);
    gemm64<1, 0, 1><<<gS, blk>>>(K, Q, S, NDIM, NDIM, CIDIM,
                                 NDIM, NDIM, NDIM, pstr, pstr, sstr,
                                 nullptr, nullptr, 0, 1.0f / (float)TDIM);

    // 3) Row softmax over j
    softmax_rows<<<BSZ * NDIM, 256>>>(S, NDIM);

    // 4) Y[c,i] = sum_j V[c,j] * S[i,j]   (CI x N x N, NT gemm)
    gemm64<0, 1, 1><<<gProj, blk>>>(V, S, Y, CIDIM, NDIM, NDIM,
                                    NDIM, NDIM, NDIM, pstr, sstr, pstr,
                                    nullptr, nullptr, 0, 1.0f);

    // 5) out[c,n] = Wo[c,:] @ Y[:,n] + bo[c] + x[c,n]   (C x CI x N)
    const dim3 gO(NDIM / 64, CDIM / 64, BSZ);
    gemm64<0, 0, 2><<<gO, blk>>>(Wo, Y, out, CDIM, NDIM, CIDIM,
                                 CIDIM, NDIM, NDIM, 0, pstr, xstr,
                                 bo, x, xstr, 1.0f);
}

// round 2
// speedup vs baseline: 1.2904x; 1.2904x over previous
#include <cuda_runtime.h>

// Problem constants
#define BSZ   2
#define CDIM  1024
#define CIDIM 512
#define NDIM  6272     // 32*14*14 = 49 * 128
#define TDIM  32

// Scratch (allocation-free rule: __device__ globals)
__device__ __align__(256) float g_K[(size_t)BSZ * CIDIM * NDIM];
__device__ __align__(256) float g_Q[(size_t)BSZ * CIDIM * NDIM];
__device__ __align__(256) float g_V[(size_t)BSZ * CIDIM * NDIM];
__device__ __align__(256) float g_Y[(size_t)BSZ * CIDIM * NDIM];
__device__ __align__(256) float g_S[(size_t)BSZ * NDIM * NDIM];   // 315 MB attention matrix

// ---------------------------------------------------------------------------
// Tiled SGEMM: C[M,N] = scale * (A op B) + epilogue
//   TA=0: A[m*lda + k]   TA=1: A[k*lda + m]
//   TB=0: B[k*ldb + n]   TB=1: B[n*ldb + k]
//   EPI=0: + bias[m]
//   EPI=1: (scale only)
//   EPI=2: + bias[m] + resid[m*ldc + n]
// Block tile 128x128, K-tile 16, 256 threads, 8x8 per-thread microtile
// (two 4-wide fragments at +0 and +64 in each dim).
// All dims are exact multiples of the tiles for this problem.
// ---------------------------------------------------------------------------
template <int TA, int TB, int EPI>
__global__ __launch_bounds__(256)
void gemm128(const float* __restrict__ Ag, const float* __restrict__ Bg,
             float* __restrict__ Cg,
             int Kd, int lda, int ldb, int ldc,
             size_t aStr, size_t bStr, size_t cStr,
             const float* __restrict__ bias,
             const float* __restrict__ resid, size_t rStr,
             float scale)
{
    const float* A = Ag + (size_t)blockIdx.z * aStr;
    const float* B = Bg + (size_t)blockIdx.z * bStr;
    float*       C = Cg + (size_t)blockIdx.z * cStr;

    __shared__ float As[16][128];
    __shared__ float Bs[16][128];

    const int tx  = threadIdx.x;           // 0..15
    const int ty  = threadIdx.y;           // 0..15
    const int tid = ty * 16 + tx;          // 0..255
    const int bm  = blockIdx.y;
    const int bn  = blockIdx.x;

    float acc[8][8] = {};

    for (int k0 = 0; k0 < Kd; k0 += 16) {
        // ---- load A tile into As[k][m] (128 rows x 16 k) ----
        if (TA == 0) {
            const int m  = tid >> 1;              // 0..127
            const int kg = (tid & 1) * 8;         // 0 or 8
            const float* ap = A + (size_t)(bm * 128 + m) * lda + k0 + kg;
            float4 a0 = *(const float4*)(ap);
            float4 a1 = *(const float4*)(ap + 4);
            As[kg + 0][m] = a0.x; As[kg + 1][m] = a0.y;
            As[kg + 2][m] = a0.z; As[kg + 3][m] = a0.w;
            As[kg + 4][m] = a1.x; As[kg + 5][m] = a1.y;
            As[kg + 6][m] = a1.z; As[kg + 7][m] = a1.w;
        } else {
            const int kk = tid >> 5;              // 0..7
            const int mg = (tid & 31) * 4;        // 0..124
            *(float4*)(&As[kk][mg]) =
                *(const float4*)(A + (size_t)(k0 + kk) * lda + bm * 128 + mg);
            *(float4*)(&As[kk + 8][mg]) =
                *(const float4*)(A + (size_t)(k0 + kk + 8) * lda + bm * 128 + mg);
        }
        // ---- load B tile into Bs[k][n] ----
        if (TB == 0) {
            const int kk = tid >> 5;
            const int ng = (tid & 31) * 4;
            *(float4*)(&Bs[kk][ng]) =
                *(const float4*)(B + (size_t)(k0 + kk) * ldb + bn * 128 + ng);
            *(float4*)(&Bs[kk + 8][ng]) =
                *(const float4*)(B + (size_t)(k0 + kk + 8) * ldb + bn * 128 + ng);
        } else {
            const int n  = tid >> 1;
            const int kg = (tid & 1) * 8;
            const float* bp = B + (size_t)(bn * 128 + n) * ldb + k0 + kg;
            float4 b0 = *(const float4*)(bp);
            float4 b1 = *(const float4*)(bp + 4);
            Bs[kg + 0][n] = b0.x; Bs[kg + 1][n] = b0.y;
            Bs[kg + 2][n] = b0.z; Bs[kg + 3][n] = b0.w;
            Bs[kg + 4][n] = b1.x; Bs[kg + 5][n] = b1.y;
            Bs[kg + 6][n] = b1.z; Bs[kg + 7][n] = b1.w;
        }
        __syncthreads();

        #pragma unroll
        for (int kk = 0; kk < 16; kk++) {
            float a[8], b[8];
            float4 t;
            t = *(const float4*)(&As[kk][ty * 4]);
            a[0] = t.x; a[1] = t.y; a[2] = t.z; a[3] = t.w;
            t = *(const float4*)(&As[kk][64 + ty * 4]);
            a[4] = t.x; a[5] = t.y; a[6] = t.z; a[7] = t.w;
            t = *(const float4*)(&Bs[kk][tx * 4]);
            b[0] = t.x; b[1] = t.y; b[2] = t.z; b[3] = t.w;
            t = *(const float4*)(&Bs[kk][64 + tx * 4]);
            b[4] = t.x; b[5] = t.y; b[6] = t.z; b[7] = t.w;
            #pragma unroll
            for (int i = 0; i < 8; i++)
                #pragma unroll
                for (int j = 0; j < 8; j++)
                    acc[i][j] += a[i] * b[j];
        }
        __syncthreads();
    }

    // ---- epilogue ----
    #pragma unroll
    for (int i = 0; i < 8; i++) {
        const int m = bm * 128 + ((i < 4) ? (ty * 4 + i) : (64 + ty * 4 + i - 4));
        float bi = 0.f;
        if (EPI == 0 || EPI == 2) bi = bias[m];
        float* crow = C + (size_t)m * ldc + bn * 128;
        const float* rrow = (EPI == 2)
            ? (resid + (size_t)blockIdx.z * rStr + (size_t)m * ldc + bn * 128)
            : nullptr;
        #pragma unroll
        for (int h = 0; h < 2; h++) {
            const int n = h * 64 + tx * 4;
            float4 v;
            v.x = acc[i][h * 4 + 0] * scale + bi;
            v.y = acc[i][h * 4 + 1] * scale + bi;
            v.z = acc[i][h * 4 + 2] * scale + bi;
            v.w = acc[i][h * 4 + 3] * scale + bi;
            if (EPI == 2) {
                float4 r = *(const float4*)(rrow + n);
                v.x += r.x; v.y += r.y; v.z += r.z; v.w += r.w;
            }
            *(float4*)(crow + n) = v;
        }
    }
}

// ---------------------------------------------------------------------------
// Row softmax over last axis. One block (256 thr) per row of length n=6272.
// ---------------------------------------------------------------------------
#define SM_VPT 25   // ceil(6272/256)
__global__ __launch_bounds__(256)
void softmax_rows(float* __restrict__ a, int n)
{
    float* row = a + (size_t)blockIdx.x * n;
    const int t = threadIdx.x;
    __shared__ float red[256];

    float vals[SM_VPT];
    float mx = -3.402823466e38f;
    #pragma unroll
    for (int v = 0; v < SM_VPT; v++) {
        int j = v * 256 + t;
        if (j < n) { vals[v] = row[j]; mx = fmaxf(mx, vals[v]); }
        else vals[v] = -3.402823466e38f;
    }
    red[t] = mx; __syncthreads();
    for (int s = 128; s > 0; s >>= 1) {
        if (t < s) red[t] = fmaxf(red[t], red[t + s]);
        __syncthreads();
    }
    mx = red[0];
    __syncthreads();

    float sum = 0.f;
    #pragma unroll
    for (int v = 0; v < SM_VPT; v++) {
        int j = v * 256 + t;
        if (j < n) { vals[v] = __expf(vals[v] - mx); sum += vals[v]; }
    }
    red[t] = sum; __syncthreads();
    for (int s = 128; s > 0; s >>= 1) {
        if (t < s) red[t] += red[t + s];
        __syncthreads();
    }
    const float inv = 1.f / red[0];

    #pragma unroll
    for (int v = 0; v < SM_VPT; v++) {
        int j = v * 256 + t;
        if (j < n) row[j] = vals[v] * inv;
    }
}

// ---------------------------------------------------------------------------
extern "C" void kernel_launch(void* const* d_in, const int* in_sizes, int n_in,
                              void* d_out, int out_size)
{
    const float* x  = (const float*)d_in[0];   // (B, C, N)
    const float* Wk = (const float*)d_in[1];   // (CI, C)
    const float* bk = (const float*)d_in[2];
    const float* Wq = (const float*)d_in[3];
    const float* bq = (const float*)d_in[4];
    const float* Wv = (const float*)d_in[5];
    const float* bv = (const float*)d_in[6];
    const float* Wo = (const float*)d_in[7];   // (C, CI)
    const float* bo = (const float*)d_in[8];
    float* out = (float*)d_out;                // (B, C, N)

    float *K, *Q, *V, *Y, *S;
    cudaGetSymbolAddress((void**)&K, g_K);
    cudaGetSymbolAddress((void**)&Q, g_Q);
    cudaGetSymbolAddress((void**)&V, g_V);
    cudaGetSymbolAddress((void**)&Y, g_Y);
    cudaGetSymbolAddress((void**)&S, g_S);

    const dim3 blk(16, 16);
    const size_t pstr = (size_t)CIDIM * NDIM;        // per-batch stride of K/Q/V/Y
    const size_t xstr = (size_t)CDIM * NDIM;         // per-batch stride of x/out
    const size_t sstr = (size_t)NDIM * NDIM;         // per-batch stride of S

    // 1) Projections: P[d,n] = W[d,:] @ x[b,:,n] + b[d]   (M=CI=512, N=6272, K=C=1024)
    const dim3 gProj(NDIM / 128, CIDIM / 128, BSZ);
    gemm128<0, 0, 0><<<gProj, blk>>>(Wk, x, K, CDIM,
                                     CDIM, NDIM, NDIM, 0, xstr, pstr,
                                     bk, nullptr, 0, 1.0f);
    gemm128<0, 0, 0><<<gProj, blk>>>(Wq, x, Q, CDIM,
                                     CDIM, NDIM, NDIM, 0, xstr, pstr,
                                     bq, nullptr, 0, 1.0f);
    gemm128<0, 0, 0><<<gProj, blk>>>(Wv, x, V, CDIM,
                                     CDIM, NDIM, NDIM, 0, xstr, pstr,
                                     bv, nullptr, 0, 1.0f);

    // 2) Scores: S[i,j] = (1/T) * sum_d K[d,i] * Q[d,j]   (M=N=6272, K=512, TN gemm)
    const dim3 gS(NDIM / 128, NDIM / 128, BSZ);
    gemm128<1, 0, 1><<<gS, blk>>>(K, Q, S, CIDIM,
                                  NDIM, NDIM, NDIM, pstr, pstr, sstr,
                                  nullptr, nullptr, 0, 1.0f / (float)TDIM);

    // 3) Row softmax over j
    softmax_rows<<<BSZ * NDIM, 256>>>(S, NDIM);

    // 4) Y[c,i] = sum_j V[c,j] * S[i,j]   (M=512, N=6272, K=6272, NT gemm)
    gemm128<0, 1, 1><<<gProj, blk>>>(V, S, Y, NDIM,
                                     NDIM, NDIM, NDIM, pstr, sstr, pstr,
                                     nullptr, nullptr, 0, 1.0f);

    // 5) out[c,n] = Wo[c,:] @ Y[:,n] + bo[c] + x[c,n]   (M=1024, N=6272, K=512)
    const dim3 gO(NDIM / 128, CDIM / 128, BSZ);
    gemm128<0, 0, 2><<<gO, blk>>>(Wo, Y, out, CIDIM,
                                  CIDIM, NDIM, NDIM, 0, pstr, xstr,
                                  bo, x, xstr, 1.0f);
}

// round 4
// speedup vs baseline: 2.2855x; 1.7711x over previous
#include <cuda_runtime.h>
#include <cuda_bf16.h>
#include <cstdint>

// Problem constants
#define BSZ   2
#define CDIM  1024
#define CIDIM 512
#define NDIM  6272     // 32*14*14 = 49*128
#define TDIM  32

// fp32 scratch (allocation-free rule: __device__ globals)
__device__ __align__(256) float g_xT[(size_t)BSZ * NDIM * CDIM];   // x^T  (B, N, C)
__device__ __align__(256) float g_Kt[(size_t)BSZ * NDIM * CIDIM];  // K^T  (B, N, CI)
__device__ __align__(256) float g_Qt[(size_t)BSZ * NDIM * CIDIM];
__device__ __align__(256) float g_V [(size_t)BSZ * CIDIM * NDIM];  // V    (B, CI, N)
__device__ __align__(256) float g_Yt[(size_t)BSZ * NDIM * CIDIM];  // Y^T  (B, N, CI)
__device__ __align__(256) float g_S [(size_t)BSZ * NDIM * NDIM];   // scores (B, N, N)

// ---------------------------------------------------------------------------
__device__ __forceinline__ uint32_t smem_u32(const void* p) {
    uint32_t a;
    asm("{ .reg .u64 t; cvta.to.shared.u64 t, %1; cvt.u32.u64 %0, t; }"
        : "=r"(a) : "l"(p));
    return a;
}

#define LDSM4(rr, addr) \
    asm volatile("ldmatrix.sync.aligned.m8n8.x4.shared.b16 {%0,%1,%2,%3}, [%4];" \
        : "=r"((rr)[0]), "=r"((rr)[1]), "=r"((rr)[2]), "=r"((rr)[3]) : "r"(addr))

#define MMA(dd, aa, b0v, b1v) \
    asm volatile("mma.sync.aligned.m16n8k16.row.col.f32.bf16.bf16.f32 " \
        "{%0,%1,%2,%3}, {%4,%5,%6,%7}, {%8,%9}, {%0,%1,%2,%3};" \
        : "+f"((dd)[0]), "+f"((dd)[1]), "+f"((dd)[2]), "+f"((dd)[3]) \
        : "r"((aa)[0]), "r"((aa)[1]), "r"((aa)[2]), "r"((aa)[3]), \
          "r"(b0v), "r"(b1v))

// SMEM: per stage 4 tiles (Ah, Al, Bh, Bl), each 128 rows x 80 bytes
#define ROWB   80u
#define TILEB  (128u * ROWB)     // 10240
#define STAGEB (4u * TILEB)      // 40960
#define SMEMSZ (2u * STAGEB)     // 81920

__device__ __forceinline__ uint32_t pack_bf(float a, float b) {
    __nv_bfloat16 ha = __float2bfloat16(a);
    __nv_bfloat16 hb = __float2bfloat16(b);
    return (uint32_t)__bfloat16_as_ushort(ha)
         | ((uint32_t)__bfloat16_as_ushort(hb) << 16);
}

// ---------------------------------------------------------------------------
// mma.sync split-bf16 GEMM:  D[i,j] = scale * sum_k A[i,k]*B[j,k] + epilogue
// A: M x K (K-major, lda), B: N' x K (K-major, ldb), C: M x N' (ldc)
// grid: (N'/128, M/128, batch), 256 threads, warp grid 2x4, warp tile 64x32.
// EPI: 0 = scale only; 1 = + bias[j]; 2 = + bias[i]; 3 = + bias[i] + resid
// ---------------------------------------------------------------------------
template <int EPI>
__global__ __launch_bounds__(256)
void tgemm(const float* __restrict__ Ag, const float* __restrict__ Bg,
           float* __restrict__ Cg, int Kd, int lda, int ldb, int ldc,
           size_t aStr, size_t bStr, size_t cStr,
           const float* __restrict__ bias,
           const float* __restrict__ resid, size_t rStr, float scale)
{
    extern __shared__ __align__(128) char smem[];
    const int tid  = threadIdx.x;
    const int lane = tid & 31;
    const int wid  = tid >> 5;
    const int wm   = wid >> 2;        // 0..1
    const int wn   = wid & 3;         // 0..3

    const float* A = Ag + (size_t)blockIdx.z * aStr;
    const float* B = Bg + (size_t)blockIdx.z * bStr;
    float*       C = Cg + (size_t)blockIdx.z * cStr;
    const int rowA = blockIdx.y * 128;
    const int rowB = blockIdx.x * 128;

    const uint32_t sb = smem_u32(smem);

    // ldmatrix base addresses (add stage offset, mi/np strides, ks*32 later)
    const uint32_t aAddr = sb
        + (uint32_t)(wm * 64 + (lane & 15)) * ROWB + (uint32_t)(lane >> 4) * 16;
    const int bq = lane >> 3;
    const uint32_t bAddr = sb + 2 * TILEB
        + (uint32_t)(wn * 32 + (bq >> 1) * 8 + (lane & 7)) * ROWB
        + (uint32_t)(bq & 1) * 16;

    float d[4][4][4];
    #pragma unroll
    for (int i = 0; i < 4; i++)
        #pragma unroll
        for (int j = 0; j < 4; j++)
            #pragma unroll
            for (int q = 0; q < 4; q++) d[i][j][q] = 0.f;

    const int nk = Kd / 32;
    float4 pa[4], pb[4];

    auto LDG = [&](int c) {
        const float* Ac = A + c * 32;
        const float* Bc = B + c * 32;
        #pragma unroll
        for (int r = 0; r < 4; r++) {
            const int idx = r * 256 + tid;
            const int row = idx >> 3, c4 = idx & 7;
            pa[r] = *(const float4*)(Ac + (size_t)(rowA + row) * lda + c4 * 4);
            pb[r] = *(const float4*)(Bc + (size_t)(rowB + row) * ldb + c4 * 4);
        }
    };

    auto STS = [&](int s) {
        char* st = smem + s * STAGEB;
        #pragma unroll
        for (int r = 0; r < 4; r++) {
            const int idx = r * 256 + tid;
            const int row = idx >> 3, c4 = idx & 7;
            const uint32_t off = row * ROWB + c4 * 8;
            {
                float4 v = pa[r];
                uint32_t h0 = pack_bf(v.x, v.y), h1 = pack_bf(v.z, v.w);
                float lx = v.x - __bfloat162float(__float2bfloat16(v.x));
                float ly = v.y - __bfloat162float(__float2bfloat16(v.y));
                float lz = v.z - __bfloat162float(__float2bfloat16(v.z));
                float lw = v.w - __bfloat162float(__float2bfloat16(v.w));
                *(uint2*)(st + off)         = make_uint2(h0, h1);
                *(uint2*)(st + TILEB + off) = make_uint2(pack_bf(lx, ly), pack_bf(lz, lw));
            }
            {
                float4 v = pb[r];
                uint32_t h0 = pack_bf(v.x, v.y), h1 = pack_bf(v.z, v.w);
                float lx = v.x - __bfloat162float(__float2bfloat16(v.x));
                float ly = v.y - __bfloat162float(__float2bfloat16(v.y));
                float lz = v.z - __bfloat162float(__float2bfloat16(v.z));
                float lw = v.w - __bfloat162float(__float2bfloat16(v.w));
                *(uint2*)(st + 2 * TILEB + off) = make_uint2(h0, h1);
                *(uint2*)(st + 3 * TILEB + off) = make_uint2(pack_bf(lx, ly), pack_bf(lz, lw));
            }
        }
    };

    auto COMPUTE = [&](int s) {
        const uint32_t so = s * STAGEB;
        #pragma unroll
        for (int ks = 0; ks < 2; ks++) {
            const uint32_t ab = aAddr + so + ks * 32;
            const uint32_t bb = bAddr + so + ks * 32;
            uint32_t ah[4][4], al[4][4], bh[2][4], bl[2][4];
            #pragma unroll
            for (int mi = 0; mi < 4; mi++) {
                LDSM4(ah[mi], ab + mi * 16 * ROWB);
                LDSM4(al[mi], ab + TILEB + mi * 16 * ROWB);
            }
            #pragma unroll
            for (int np = 0; np < 2; np++) {
                LDSM4(bh[np], bb + np * 16 * ROWB);
                LDSM4(bl[np], bb + TILEB + np * 16 * ROWB);
            }
            #pragma unroll
            for (int mi = 0; mi < 4; mi++)
                #pragma unroll
                for (int ni = 0; ni < 4; ni++) {
                    const int np = ni >> 1, h = (ni & 1) * 2;
                    MMA(d[mi][ni], ah[mi], bh[np][h], bh[np][h + 1]);
                    MMA(d[mi][ni], ah[mi], bl[np][h], bl[np][h + 1]);
                    MMA(d[mi][ni], al[mi], bh[np][h], bh[np][h + 1]);
                }
        }
    };

    LDG(0); STS(0); __syncthreads();
    for (int c = 0; c < nk; c++) {
        const int s = c & 1;
        if (c + 1 < nk) LDG(c + 1);
        COMPUTE(s);
        if (c + 1 < nk) {
            __syncthreads();
            STS(s ^ 1);
            __syncthreads();
        }
    }

    // ---- epilogue ----
    const int r0base = rowA + wm * 64;
    const int c0base = rowB + wn * 32;
    #pragma unroll
    for (int mi = 0; mi < 4; mi++) {
        const int row0 = r0base + mi * 16 + (lane >> 2);
        const int row1 = row0 + 8;
        float bi0 = 0.f, bi1 = 0.f;
        if (EPI == 2 || EPI == 3) { bi0 = bias[row0]; bi1 = bias[row1]; }
        #pragma unroll
        for (int ni = 0; ni < 4; ni++) {
            const int col = c0base + ni * 8 + (lane & 3) * 2;
            float2 v0, v1;
            v0.x = d[mi][ni][0] * scale; v0.y = d[mi][ni][1] * scale;
            v1.x = d[mi][ni][2] * scale; v1.y = d[mi][ni][3] * scale;
            if (EPI == 1) {
                float2 bb = *(const float2*)(bias + col);
                v0.x += bb.x; v0.y += bb.y; v1.x += bb.x; v1.y += bb.y;
            }
            if (EPI == 2 || EPI == 3) {
                v0.x += bi0; v0.y += bi0; v1.x += bi1; v1.y += bi1;
            }
            if (EPI == 3) {
                const float* rb = resid + (size_t)blockIdx.z * rStr;
                float2 q0 = *(const float2*)(rb + (size_t)row0 * ldc + col);
                float2 q1 = *(const float2*)(rb + (size_t)row1 * ldc + col);
                v0.x += q0.x; v0.y += q0.y; v1.x += q1.x; v1.y += q1.y;
            }
            *(float2*)(C + (size_t)row0 * ldc + col) = v0;
            *(float2*)(C + (size_t)row1 * ldc + col) = v1;
        }
    }
}

// ---------------------------------------------------------------------------
// 32x32 tiled transpose: (C, N) -> (N, C) per batch
// ---------------------------------------------------------------------------
__global__ __launch_bounds__(256)
void transpose_CN(const float* __restrict__ src, float* __restrict__ dst)
{
    __shared__ float t[32][33];
    const float* s = src + (size_t)blockIdx.z * CDIM * NDIM;
    float*       d = dst + (size_t)blockIdx.z * NDIM * CDIM;
    const int n0 = blockIdx.x * 32;
    const int c0 = blockIdx.y * 32;
    const int tx = threadIdx.x, ty = threadIdx.y;
    #pragma unroll
    for (int r = 0; r < 4; r++)
        t[ty + r * 8][tx] = s[(size_t)(c0 + ty + r * 8) * NDIM + n0 + tx];
    __syncthreads();
    #pragma unroll
    for (int r = 0; r < 4; r++)
        d[(size_t)(n0 + ty + r * 8) * CDIM + c0 + tx] = t[tx][ty + r * 8];
}

// ---------------------------------------------------------------------------
// Row softmax, one 256-thread block per row of length 6272
// ---------------------------------------------------------------------------
#define SM_VPT 25
__global__ __launch_bounds__(256)
void softmax_rows(float* __restrict__ a, int n)
{
    float* row = a + (size_t)blockIdx.x * n;
    const int t = threadIdx.x;
    __shared__ float red[256];

    float vals[SM_VPT];
    float mx = -3.402823466e38f;
    #pragma unroll
    for (int v = 0; v < SM_VPT; v++) {
        int j = v * 256 + t;
        if (j < n) { vals[v] = row[j]; mx = fmaxf(mx, vals[v]); }
        else vals[v] = -3.402823466e38f;
    }
    red[t] = mx; __syncthreads();
    for (int s = 128; s > 0; s >>= 1) {
        if (t < s) red[t] = fmaxf(red[t], red[t + s]);
        __syncthreads();
    }
    mx = red[0];
    __syncthreads();

    float sum = 0.f;
    #pragma unroll
    for (int v = 0; v < SM_VPT; v++) {
        int j = v * 256 + t;
        if (j < n) { vals[v] = __expf(vals[v] - mx); sum += vals[v]; }
    }
    red[t] = sum; __syncthreads();
    for (int s = 128; s > 0; s >>= 1) {
        if (t < s) red[t] += red[t + s];
        __syncthreads();
    }
    const float inv = 1.f / red[0];

    #pragma unroll
    for (int v = 0; v < SM_VPT; v++) {
        int j = v * 256 + t;
        if (j < n) row[j] = vals[v] * inv;
    }
}

// ---------------------------------------------------------------------------
extern "C" void kernel_launch(void* const* d_in, const int* in_sizes, int n_in,
                              void* d_out, int out_size)
{
    const float* x  = (const float*)d_in[0];   // (B, C, N)
    const float* Wk = (const float*)d_in[1];   // (CI, C)
    const float* bk = (const float*)d_in[2];
    const float* Wq = (const float*)d_in[3];
    const float* bq = (const float*)d_in[4];
    const float* Wv = (const float*)d_in[5];
    const float* bv = (const float*)d_in[6];
    const float* Wo = (const float*)d_in[7];   // (C, CI)
    const float* bo = (const float*)d_in[8];
    float* out = (float*)d_out;                // (B, C, N)

    float *xT, *Kt, *Qt, *V, *Yt, *S;
    cudaGetSymbolAddress((void**)&xT, g_xT);
    cudaGetSymbolAddress((void**)&Kt, g_Kt);
    cudaGetSymbolAddress((void**)&Qt, g_Qt);
    cudaGetSymbolAddress((void**)&V,  g_V);
    cudaGetSymbolAddress((void**)&Yt, g_Yt);
    cudaGetSymbolAddress((void**)&S,  g_S);

    cudaFuncSetAttribute(tgemm<0>, cudaFuncAttributeMaxDynamicSharedMemorySize, SMEMSZ);
    cudaFuncSetAttribute(tgemm<1>, cudaFuncAttributeMaxDynamicSharedMemorySize, SMEMSZ);
    cudaFuncSetAttribute(tgemm<2>, cudaFuncAttributeMaxDynamicSharedMemorySize, SMEMSZ);
    cudaFuncSetAttribute(tgemm<3>, cudaFuncAttributeMaxDynamicSharedMemorySize, SMEMSZ);

    const size_t pstr = (size_t)NDIM * CIDIM;   // Kt/Qt/Yt batch stride
    const size_t vstr = (size_t)CIDIM * NDIM;   // V batch stride
    const size_t xstr = (size_t)CDIM * NDIM;    // x/out batch stride
    const size_t tstr = (size_t)NDIM * CDIM;    // xT batch stride
    const size_t sstr = (size_t)NDIM * NDIM;    // S batch stride

    // 0) xT = transpose(x)
    transpose_CN<<<dim3(NDIM / 32, CDIM / 32, BSZ), dim3(32, 8)>>>(x, xT);

    // 1) Kt[n,d] = xT[n,:]·Wk[d,:] + bk[d];  Qt likewise  (M=6272, N'=512, K=1024)
    const dim3 gKQ(CIDIM / 128, NDIM / 128, BSZ);
    tgemm<1><<<gKQ, 256, SMEMSZ>>>(xT, Wk, Kt, CDIM, CDIM, CDIM, CIDIM,
                                   tstr, 0, pstr, bk, nullptr, 0, 1.0f);
    tgemm<1><<<gKQ, 256, SMEMSZ>>>(xT, Wq, Qt, CDIM, CDIM, CDIM, CIDIM,
                                   tstr, 0, pstr, bq, nullptr, 0, 1.0f);

    // 2) V[d,n] = Wv[d,:]·xT[n,:] + bv[d]   (M=512, N'=6272, K=1024)
    const dim3 gV(NDIM / 128, CIDIM / 128, BSZ);
    tgemm<2><<<gV, 256, SMEMSZ>>>(Wv, xT, V, CDIM, CDIM, CDIM, NDIM,
                                  0, tstr, vstr, bv, nullptr, 0, 1.0f);

    // 3) S[i,j] = (1/T) Kt[i,:]·Qt[j,:]     (M=N'=6272, K=512)
    const dim3 gS(NDIM / 128, NDIM / 128, BSZ);
    tgemm<0><<<gS, 256, SMEMSZ>>>(Kt, Qt, S, CIDIM, CIDIM, CIDIM, NDIM,
                                  pstr, pstr, sstr, nullptr, nullptr, 0,
                                  1.0f / (float)TDIM);

    // 4) softmax rows
    softmax_rows<<<BSZ * NDIM, 256>>>(S, NDIM);

    // 5) Yt[i,c] = S[i,:]·V[c,:]            (M=6272, N'=512, K=6272)
    const dim3 gY(CIDIM / 128, NDIM / 128, BSZ);
    tgemm<0><<<gY, 256, SMEMSZ>>>(S, V, Yt, NDIM, NDIM, NDIM, CIDIM,
                                  sstr, vstr, pstr, nullptr, nullptr, 0, 1.0f);

    // 6) out[c,n] = Wo[c,:]·Yt[n,:] + bo[c] + x[c,n]  (M=1024, N'=6272, K=512)
    const dim3 gO(NDIM / 128, CDIM / 128, BSZ);
    tgemm<3><<<gO, 256, SMEMSZ>>>(Wo, Yt, out, CIDIM, CIDIM, CIDIM, NDIM,
                                  0, pstr, xstr, bo, x, xstr, 1.0f);
}

// round 5
// speedup vs baseline: 3.0457x; 1.3326x over previous
#include <cuda_runtime.h>
#include <cuda_bf16.h>
#include <cstdint>

// Problem constants
#define BSZ   2
#define CDIM  1024
#define CIDIM 512
#define NDIM  6272     // 32*14*14 = 49*128
#define TDIM  32

// bf16 hi/lo scratch (allocation-free rule: __device__ globals)
__device__ __align__(256) __nv_bfloat16 g_xTh[(size_t)BSZ * NDIM * CDIM];
__device__ __align__(256) __nv_bfloat16 g_xTl[(size_t)BSZ * NDIM * CDIM];
__device__ __align__(256) __nv_bfloat16 g_Wkh[CIDIM * CDIM];
__device__ __align__(256) __nv_bfloat16 g_Wkl[CIDIM * CDIM];
__device__ __align__(256) __nv_bfloat16 g_Wqh[CIDIM * CDIM];
__device__ __align__(256) __nv_bfloat16 g_Wql[CIDIM * CDIM];
__device__ __align__(256) __nv_bfloat16 g_Wvh[CIDIM * CDIM];
__device__ __align__(256) __nv_bfloat16 g_Wvl[CIDIM * CDIM];
__device__ __align__(256) __nv_bfloat16 g_Woh[CDIM * CIDIM];
__device__ __align__(256) __nv_bfloat16 g_Wol[CDIM * CIDIM];
__device__ __align__(256) __nv_bfloat16 g_Kth[(size_t)BSZ * NDIM * CIDIM];
__device__ __align__(256) __nv_bfloat16 g_Ktl[(size_t)BSZ * NDIM * CIDIM];
__device__ __align__(256) __nv_bfloat16 g_Qth[(size_t)BSZ * NDIM * CIDIM];
__device__ __align__(256) __nv_bfloat16 g_Qtl[(size_t)BSZ * NDIM * CIDIM];
__device__ __align__(256) __nv_bfloat16 g_Vh [(size_t)BSZ * CIDIM * NDIM];
__device__ __align__(256) __nv_bfloat16 g_Vl [(size_t)BSZ * CIDIM * NDIM];
__device__ __align__(256) __nv_bfloat16 g_Yth[(size_t)BSZ * NDIM * CIDIM];
__device__ __align__(256) __nv_bfloat16 g_Ytl[(size_t)BSZ * NDIM * CIDIM];
__device__ __align__(256) float         g_S  [(size_t)BSZ * NDIM * NDIM];   // fp32 scores
__device__ __align__(256) __nv_bfloat16 g_Ph [(size_t)BSZ * NDIM * NDIM];
__device__ __align__(256) __nv_bfloat16 g_Pl [(size_t)BSZ * NDIM * NDIM];

// ---------------------------------------------------------------------------
__device__ __forceinline__ uint32_t smem_u32(const void* p) {
    uint32_t a;
    asm("{ .reg .u64 t; cvta.to.shared.u64 t, %1; cvt.u32.u64 %0, t; }"
        : "=r"(a) : "l"(p));
    return a;
}

#define LDSM4(rr, addr) \
    asm volatile("ldmatrix.sync.aligned.m8n8.x4.shared.b16 {%0,%1,%2,%3}, [%4];" \
        : "=r"((rr)[0]), "=r"((rr)[1]), "=r"((rr)[2]), "=r"((rr)[3]) : "r"(addr))

#define MMA(dd, aa, b0v, b1v) \
    asm volatile("mma.sync.aligned.m16n8k16.row.col.f32.bf16.bf16.f32 " \
        "{%0,%1,%2,%3}, {%4,%5,%6,%7}, {%8,%9}, {%0,%1,%2,%3};" \
        : "+f"((dd)[0]), "+f"((dd)[1]), "+f"((dd)[2]), "+f"((dd)[3]) \
        : "r"((aa)[0]), "r"((aa)[1]), "r"((aa)[2]), "r"((aa)[3]), \
          "r"(b0v), "r"(b1v))

#define CP16(dst, src) \
    asm volatile("cp.async.cg.shared.global [%0], [%1], 16;" :: "r"(dst), "l"(src))
#define CP_COMMIT() asm volatile("cp.async.commit_group;" ::: "memory")
#define CP_WAIT1()  asm volatile("cp.async.wait_group 1;" ::: "memory")
#define CP_WAIT0()  asm volatile("cp.async.wait_group 0;" ::: "memory")

// SMEM: per stage 4 tiles (Ah, Al, Bh, Bl), each 128 rows x 80B (64B data + pad)
#define ROWB   80u
#define TILEB  (128u * ROWB)     // 10240
#define STAGEB (4u * TILEB)      // 40960
#define SMEMSZ (2u * STAGEB)     // 81920

__device__ __forceinline__ void split2(float a, float b, uint32_t& hi, uint32_t& lo) {
    __nv_bfloat16 ha = __float2bfloat16(a);
    __nv_bfloat16 hb = __float2bfloat16(b);
    __nv_bfloat16 la = __float2bfloat16(a - __bfloat162float(ha));
    __nv_bfloat16 lb = __float2bfloat16(b - __bfloat162float(hb));
    hi = (uint32_t)__bfloat16_as_ushort(ha) | ((uint32_t)__bfloat16_as_ushort(hb) << 16);
    lo = (uint32_t)__bfloat16_as_ushort(la) | ((uint32_t)__bfloat16_as_ushort(lb) << 16);
}

// ---------------------------------------------------------------------------
// Split-bf16 GEMM on pre-split operands:
//   acc[i,j] = sum_k ( Ah*Bh + Ah*Bl + Al*Bh )[i,k][j,k]
// A: M x K (K-major), B: N' x K (K-major), all ld = Kd.
// grid (N'/128, M/128, Z), 256 thr, warp grid 2x4, warp tile 64x32, cp.async x2.
// EPI: 0 = f32 out, scale
//      1 = split out + bias[col], DUAL (z = 2*BSZ: second half uses B2/C2/bias2)
//      2 = split out + bias[row]
//      3 = split out, no bias
//      4 = f32 out + bias[row] + resid
// ---------------------------------------------------------------------------
template <int EPI>
__global__ __launch_bounds__(256, 2)
void tgemm(const __nv_bfloat16* __restrict__ Ah, const __nv_bfloat16* __restrict__ Al,
           const __nv_bfloat16* __restrict__ Bh, const __nv_bfloat16* __restrict__ Bl,
           const __nv_bfloat16* __restrict__ B2h, const __nv_bfloat16* __restrict__ B2l,
           float* __restrict__ Cf,
           __nv_bfloat16* __restrict__ Chi, __nv_bfloat16* __restrict__ Clo,
           __nv_bfloat16* __restrict__ C2hi, __nv_bfloat16* __restrict__ C2lo,
           int Kd, int ldc, size_t aStr, size_t bStr, size_t cStr,
           const float* __restrict__ bias, const float* __restrict__ bias2,
           const float* __restrict__ resid, size_t rStr, float scale)
{
    extern __shared__ __align__(128) char smem[];
    const int tid  = threadIdx.x;
    const int lane = tid & 31;
    const int wid  = tid >> 5;
    const int wm   = wid >> 2;
    const int wn   = wid & 3;

    int batch, sel = 0;
    if (EPI == 1) { batch = blockIdx.z & 1; sel = blockIdx.z >> 1; }
    else          { batch = blockIdx.z; }

    const __nv_bfloat16* Ap  = Ah + (size_t)batch * aStr;
    const __nv_bfloat16* Alp = Al + (size_t)batch * aStr;
    const __nv_bfloat16* Bp  = (EPI == 1 && sel) ? B2h : Bh;
    const __nv_bfloat16* Blp = (EPI == 1 && sel) ? B2l : Bl;
    Bp  += (size_t)batch * bStr;
    Blp += (size_t)batch * bStr;

    const int rowA = blockIdx.y * 128;
    const int rowB = blockIdx.x * 128;
    const uint32_t sb = smem_u32(smem);

    // ldmatrix addresses
    const uint32_t aAddr = sb
        + (uint32_t)(wm * 64 + (lane & 15)) * ROWB + (uint32_t)(lane >> 4) * 16;
    const int bq = lane >> 3;
    const uint32_t bAddr = sb + 2 * TILEB
        + (uint32_t)(wn * 32 + (bq >> 1) * 8 + (lane & 7)) * ROWB
        + (uint32_t)(bq & 1) * 16;

    float d[4][4][4];
    #pragma unroll
    for (int i = 0; i < 4; i++)
        #pragma unroll
        for (int j = 0; j < 4; j++)
            #pragma unroll
            for (int q = 0; q < 4; q++) d[i][j][q] = 0.f;

    const int nk = Kd / 32;

    auto LOAD = [&](int kc, int s) {
        const uint32_t so = sb + (uint32_t)s * STAGEB;
        const int k0 = kc * 32;
        #pragma unroll
        for (int t = 0; t < 4; t++) {
            const __nv_bfloat16* src =
                (t == 0) ? Ap : (t == 1) ? Alp : (t == 2) ? Bp : Blp;
            const int rb = (t < 2) ? rowA : rowB;
            #pragma unroll
            for (int r = 0; r < 2; r++) {
                const int idx = r * 256 + tid;
                const int row = idx >> 2;
                const int c8  = (idx & 3) * 8;
                const uint32_t dst = so + (uint32_t)t * TILEB
                                   + (uint32_t)row * ROWB + (uint32_t)(c8 * 2);
                const void* g = src + (size_t)(rb + row) * Kd + k0 + c8;
                CP16(dst, g);
            }
        }
        CP_COMMIT();
    };

    auto COMPUTE = [&](int s) {
        const uint32_t so = (uint32_t)s * STAGEB;
        #pragma unroll
        for (int ks = 0; ks < 2; ks++) {
            const uint32_t ab = aAddr + so + ks * 32;
            const uint32_t bb = bAddr + so + ks * 32;
            uint32_t ah[4][4], al[4][4], bh[2][4], bl[2][4];
            #pragma unroll
            for (int mi = 0; mi < 4; mi++) {
                LDSM4(ah[mi], ab + mi * 16 * ROWB);
                LDSM4(al[mi], ab + TILEB + mi * 16 * ROWB);
            }
            #pragma unroll
            for (int np = 0; np < 2; np++) {
                LDSM4(bh[np], bb + np * 16 * ROWB);
                LDSM4(bl[np], bb + TILEB + np * 16 * ROWB);
            }
            #pragma unroll
            for (int mi = 0; mi < 4; mi++)
                #pragma unroll
                for (int ni = 0; ni < 4; ni++) {
                    const int np = ni >> 1, h = (ni & 1) * 2;
                    MMA(d[mi][ni], ah[mi], bh[np][h], bh[np][h + 1]);
                    MMA(d[mi][ni], ah[mi], bl[np][h], bl[np][h + 1]);
                    MMA(d[mi][ni], al[mi], bh[np][h], bh[np][h + 1]);
                }
        }
    };

    LOAD(0, 0);
    for (int c = 0; c < nk; c++) {
        const int s = c & 1;
        if (c + 1 < nk) { LOAD(c + 1, s ^ 1); CP_WAIT1(); }
        else            { CP_WAIT0(); }
        __syncthreads();
        COMPUTE(s);
        __syncthreads();
    }

    // ---- epilogue ----
    float* Cfp = (EPI == 0 || EPI == 4) ? (Cf + (size_t)batch * cStr) : nullptr;
    __nv_bfloat16* Ch = nullptr; __nv_bfloat16* Cl = nullptr;
    if (EPI == 1 || EPI == 2 || EPI == 3) {
        Ch = ((EPI == 1 && sel) ? C2hi : Chi) + (size_t)batch * cStr;
        Cl = ((EPI == 1 && sel) ? C2lo : Clo) + (size_t)batch * cStr;
    }
    const float* bp = (EPI == 1 && sel) ? bias2 : bias;

    const int r0base = rowA + wm * 64;
    const int c0base = rowB + wn * 32;
    #pragma unroll
    for (int mi = 0; mi < 4; mi++) {
        const int row0 = r0base + mi * 16 + (lane >> 2);
        const int row1 = row0 + 8;
        float bi0 = 0.f, bi1 = 0.f;
        if (EPI == 2 || EPI == 4) { bi0 = bp[row0]; bi1 = bp[row1]; }
        #pragma unroll
        for (int ni = 0; ni < 4; ni++) {
            const int col = c0base + ni * 8 + (lane & 3) * 2;
            float v00 = d[mi][ni][0] * scale, v01 = d[mi][ni][1] * scale;
            float v10 = d[mi][ni][2] * scale, v11 = d[mi][ni][3] * scale;
            if (EPI == 1) {
                float b0 = bp[col], b1 = bp[col + 1];
                v00 += b0; v01 += b1; v10 += b0; v11 += b1;
            }
            if (EPI == 2 || EPI == 4) { v00 += bi0; v01 += bi0; v10 += bi1; v11 += bi1; }
            if (EPI == 4) {
                const float* rb = resid + (size_t)batch * rStr;
                float2 q0 = *(const float2*)(rb + (size_t)row0 * ldc + col);
                float2 q1 = *(const float2*)(rb + (size_t)row1 * ldc + col);
                v00 += q0.x; v01 += q0.y; v10 += q1.x; v11 += q1.y;
            }
            if (EPI == 0 || EPI == 4) {
                *(float2*)(Cfp + (size_t)row0 * ldc + col) = make_float2(v00, v01);
                *(float2*)(Cfp + (size_t)row1 * ldc + col) = make_float2(v10, v11);
            } else {
                uint32_t h0, l0, h1, l1;
                split2(v00, v01, h0, l0);
                split2(v10, v11, h1, l1);
                *(uint32_t*)(Ch + (size_t)row0 * ldc + col) = h0;
                *(uint32_t*)(Cl + (size_t)row0 * ldc + col) = l0;
                *(uint32_t*)(Ch + (size_t)row1 * ldc + col) = h1;
                *(uint32_t*)(Cl + (size_t)row1 * ldc + col) = l1;
            }
        }
    }
}

// ---------------------------------------------------------------------------
// 32x32 tiled transpose + split: x (B,C,N) fp32 -> xT hi/lo (B,N,C) bf16
// ---------------------------------------------------------------------------
__global__ __launch_bounds__(256)
void transpose_split(const float* __restrict__ src,
                     __nv_bfloat16* __restrict__ dh, __nv_bfloat16* __restrict__ dl)
{
    __shared__ float t[32][33];
    const float* s = src + (size_t)blockIdx.z * CDIM * NDIM;
    __nv_bfloat16* oh = dh + (size_t)blockIdx.z * NDIM * CDIM;
    __nv_bfloat16* ol = dl + (size_t)blockIdx.z * NDIM * CDIM;
    const int n0 = blockIdx.x * 32;
    const int c0 = blockIdx.y * 32;
    const int tx = threadIdx.x, ty = threadIdx.y;
    #pragma unroll
    for (int r = 0; r < 4; r++)
        t[ty + r * 8][tx] = s[(size_t)(c0 + ty + r * 8) * NDIM + n0 + tx];
    __syncthreads();
    #pragma unroll
    for (int r = 0; r < 4; r++) {
        float v = t[tx][ty + r * 8];
        __nv_bfloat16 h = __float2bfloat16(v);
        __nv_bfloat16 l = __float2bfloat16(v - __bfloat162float(h));
        const size_t o = (size_t)(n0 + ty + r * 8) * CDIM + c0 + tx;
        oh[o] = h; ol[o] = l;
    }
}

// Elementwise fp32 -> bf16 hi/lo split (weights), vectorized x4
__global__ __launch_bounds__(256)
void split_mat(const float* __restrict__ src,
               __nv_bfloat16* __restrict__ dh, __nv_bfloat16* __restrict__ dl, int n4)
{
    const int i = blockIdx.x * 256 + threadIdx.x;
    if (i >= n4) return;
    float4 v = ((const float4*)src)[i];
    uint32_t h0, l0, h1, l1;
    split2(v.x, v.y, h0, l0);
    split2(v.z, v.w, h1, l1);
    ((uint2*)dh)[i] = make_uint2(h0, h1);
    ((uint2*)dl)[i] = make_uint2(l0, l1);
}

// ---------------------------------------------------------------------------
// Row softmax (fp32 in) -> probability hi/lo bf16 out
// ---------------------------------------------------------------------------
#define SM_VPT 25
__global__ __launch_bounds__(256)
void softmax_split(const float* __restrict__ S,
                   __nv_bfloat16* __restrict__ Ph, __nv_bfloat16* __restrict__ Pl, int n)
{
    const float* row = S + (size_t)blockIdx.x * n;
    __nv_bfloat16* ph = Ph + (size_t)blockIdx.x * n;
    __nv_bfloat16* pl = Pl + (size_t)blockIdx.x * n;
    const int t = threadIdx.x;
    __shared__ float red[256];

    float vals[SM_VPT];
    float mx = -3.402823466e38f;
    #pragma unroll
    for (int v = 0; v < SM_VPT; v++) {
        int j = v * 256 + t;
        if (j < n) { vals[v] = row[j]; mx = fmaxf(mx, vals[v]); }
        else vals[v] = -3.402823466e38f;
    }
    red[t] = mx; __syncthreads();
    for (int s = 128; s > 0; s >>= 1) {
        if (t < s) red[t] = fmaxf(red[t], red[t + s]);
        __syncthreads();
    }
    mx = red[0];
    __syncthreads();

    float sum = 0.f;
    #pragma unroll
    for (int v = 0; v < SM_VPT; v++) {
        int j = v * 256 + t;
        if (j < n) { vals[v] = __expf(vals[v] - mx); sum += vals[v]; }
    }
    red[t] = sum; __syncthreads();
    for (int s = 128; s > 0; s >>= 1) {
        if (t < s) red[t] += red[t + s];
        __syncthreads();
    }
    const float inv = 1.f / red[0];

    #pragma unroll
    for (int v = 0; v < SM_VPT; v++) {
        int j = v * 256 + t;
        if (j < n) {
            float p = vals[v] * inv;
            __nv_bfloat16 h = __float2bfloat16(p);
            ph[j] = h;
            pl[j] = __float2bfloat16(p - __bfloat162float(h));
        }
    }
}

// ---------------------------------------------------------------------------
extern "C" void kernel_launch(void* const* d_in, const int* in_sizes, int n_in,
                              void* d_out, int out_size)
{
    const float* x  = (const float*)d_in[0];   // (B, C, N)
    const float* Wk = (const float*)d_in[1];   // (CI, C)
    const float* bk = (const float*)d_in[2];
    const float* Wq = (const float*)d_in[3];
    const float* bq = (const float*)d_in[4];
    const float* Wv = (const float*)d_in[5];
    const float* bv = (const float*)d_in[6];
    const float* Wo = (const float*)d_in[7];   // (C, CI)
    const float* bo = (const float*)d_in[8];
    float* out = (float*)d_out;                // (B, C, N)

    __nv_bfloat16 *xTh, *xTl, *Wkh, *Wkl, *Wqh, *Wql, *Wvh, *Wvl, *Woh, *Wol;
    __nv_bfloat16 *Kth, *Ktl, *Qth, *Qtl, *Vh, *Vl, *Yth, *Ytl, *Ph, *Pl;
    float* S;
    cudaGetSymbolAddress((void**)&xTh, g_xTh); cudaGetSymbolAddress((void**)&xTl, g_xTl);
    cudaGetSymbolAddress((void**)&Wkh, g_Wkh); cudaGetSymbolAddress((void**)&Wkl, g_Wkl);
    cudaGetSymbolAddress((void**)&Wqh, g_Wqh); cudaGetSymbolAddress((void**)&Wql, g_Wql);
    cudaGetSymbolAddress((void**)&Wvh, g_Wvh); cudaGetSymbolAddress((void**)&Wvl, g_Wvl);
    cudaGetSymbolAddress((void**)&Woh, g_Woh); cudaGetSymbolAddress((void**)&Wol, g_Wol);
    cudaGetSymbolAddress((void**)&Kth, g_Kth); cudaGetSymbolAddress((void**)&Ktl, g_Ktl);
    cudaGetSymbolAddress((void**)&Qth, g_Qth); cudaGetSymbolAddress((void**)&Qtl, g_Qtl);
    cudaGetSymbolAddress((void**)&Vh,  g_Vh);  cudaGetSymbolAddress((void**)&Vl,  g_Vl);
    cudaGetSymbolAddress((void**)&Yth, g_Yth); cudaGetSymbolAddress((void**)&Ytl, g_Ytl);
    cudaGetSymbolAddress((void**)&Ph,  g_Ph);  cudaGetSymbolAddress((void**)&Pl,  g_Pl);
    cudaGetSymbolAddress((void**)&S,   g_S);

    cudaFuncSetAttribute(tgemm<0>, cudaFuncAttributeMaxDynamicSharedMemorySize, SMEMSZ);
    cudaFuncSetAttribute(tgemm<1>, cudaFuncAttributeMaxDynamicSharedMemorySize, SMEMSZ);
    cudaFuncSetAttribute(tgemm<2>, cudaFuncAttributeMaxDynamicSharedMemorySize, SMEMSZ);
    cudaFuncSetAttribute(tgemm<3>, cudaFuncAttributeMaxDynamicSharedMemorySize, SMEMSZ);
    cudaFuncSetAttribute(tgemm<4>, cudaFuncAttributeMaxDynamicSharedMemorySize, SMEMSZ);

    const size_t pstr = (size_t)NDIM * CIDIM;   // Kt/Qt/Yt batch stride (elems)
    const size_t vstr = (size_t)CIDIM * NDIM;   // V batch stride
    const size_t xstr = (size_t)CDIM * NDIM;    // x/out batch stride
    const size_t tstr = (size_t)NDIM * CDIM;    // xT batch stride
    const size_t sstr = (size_t)NDIM * NDIM;    // S/P batch stride

    const int w4 = (CIDIM * CDIM) / 4;          // all weight mats same elem count

    // 0) splits
    transpose_split<<<dim3(NDIM / 32, CDIM / 32, BSZ), dim3(32, 8)>>>(x, xTh, xTl);
    split_mat<<<(w4 + 255) / 256, 256>>>(Wk, Wkh, Wkl, w4);
    split_mat<<<(w4 + 255) / 256, 256>>>(Wq, Wqh, Wql, w4);
    split_mat<<<(w4 + 255) / 256, 256>>>(Wv, Wvh, Wvl, w4);
    split_mat<<<(w4 + 255) / 256, 256>>>(Wo, Woh, Wol, w4);

    // 1) K & Q projections (merged, DUAL): Kt/Qt[n,d] = xT[n,:]·W[d,:] + b[d]
    tgemm<1><<<dim3(CIDIM / 128, NDIM / 128, 2 * BSZ), 256, SMEMSZ>>>(
        xTh, xTl, Wkh, Wkl, Wqh, Wql,
        nullptr, Kth, Ktl, Qth, Qtl,
        CDIM, CIDIM, tstr, 0, pstr, bk, bq, nullptr, 0, 1.0f);

    // 2) V[c,n] = Wv[c,:]·xT[n,:] + bv[c]
    tgemm<2><<<dim3(NDIM / 128, CIDIM / 128, BSZ), 256, SMEMSZ>>>(
        Wvh, Wvl, xTh, xTl, nullptr, nullptr,
        nullptr, Vh, Vl, nullptr, nullptr,
        CDIM, NDIM, 0, tstr, vstr, bv, nullptr, nullptr, 0, 1.0f);

    // 3) S[i,j] = (1/T) Kt[i,:]·Qt[j,:]  (fp32 out)
    tgemm<0><<<dim3(NDIM / 128, NDIM / 128, BSZ), 256, SMEMSZ>>>(
        Kth, Ktl, Qth, Qtl, nullptr, nullptr,
        S, nullptr, nullptr, nullptr, nullptr,
        CIDIM, NDIM, pstr, pstr, sstr, nullptr, nullptr, nullptr, 0,
        1.0f / (float)TDIM);

    // 4) softmax -> P hi/lo
    softmax_split<<<BSZ * NDIM, 256>>>(S, Ph, Pl, NDIM);

    // 5) Yt[i,c] = P[i,:]·V[c,:]
    tgemm<3><<<dim3(CIDIM / 128, NDIM / 128, BSZ), 256, SMEMSZ>>>(
        Ph, Pl, Vh, Vl, nullptr, nullptr,
        nullptr, Yth, Ytl, nullptr, nullptr,
        NDIM, CIDIM, sstr, vstr, pstr, nullptr, nullptr, nullptr, 0, 1.0f);

    // 6) out[c,n] = Wo[c,:]·Yt[n,:] + bo[c] + x[c,n]  (fp32 out)
    tgemm<4><<<dim3(NDIM / 128, CDIM / 128, BSZ), 256, SMEMSZ>>>(
        Woh, Wol, Yth, Ytl, nullptr, nullptr,
        out, nullptr, nullptr, nullptr, nullptr,
        CIDIM, NDIM, 0, pstr, xstr, bo, nullptr, x, xstr, 1.0f);
}

// round 6
// speedup vs baseline: 3.2175x; 1.0564x over previous
#include <cuda_runtime.h>
#include <cuda_bf16.h>
#include <cstdint>

// Problem constants
#define BSZ   2
#define CDIM  1024
#define CIDIM 512
#define NDIM  6272     // 32*14*14 = 49*128
#define TDIM  32

// bf16 hi/lo scratch (allocation-free rule: __device__ globals)
__device__ __align__(256) __nv_bfloat16 g_xTh[(size_t)BSZ * NDIM * CDIM];
__device__ __align__(256) __nv_bfloat16 g_xTl[(size_t)BSZ * NDIM * CDIM];
__device__ __align__(256) __nv_bfloat16 g_Wkh[CIDIM * CDIM];
__device__ __align__(256) __nv_bfloat16 g_Wkl[CIDIM * CDIM];
__device__ __align__(256) __nv_bfloat16 g_Wqh[CIDIM * CDIM];
__device__ __align__(256) __nv_bfloat16 g_Wql[CIDIM * CDIM];
__device__ __align__(256) __nv_bfloat16 g_Wvh[CIDIM * CDIM];
__device__ __align__(256) __nv_bfloat16 g_Wvl[CIDIM * CDIM];
__device__ __align__(256) __nv_bfloat16 g_Woh[CDIM * CIDIM];
__device__ __align__(256) __nv_bfloat16 g_Wol[CDIM * CIDIM];
__device__ __align__(256) __nv_bfloat16 g_Kth[(size_t)BSZ * NDIM * CIDIM];
__device__ __align__(256) __nv_bfloat16 g_Ktl[(size_t)BSZ * NDIM * CIDIM];
__device__ __align__(256) __nv_bfloat16 g_Qth[(size_t)BSZ * NDIM * CIDIM];
__device__ __align__(256) __nv_bfloat16 g_Qtl[(size_t)BSZ * NDIM * CIDIM];
__device__ __align__(256) __nv_bfloat16 g_Vh [(size_t)BSZ * CIDIM * NDIM];
__device__ __align__(256) __nv_bfloat16 g_Vl [(size_t)BSZ * CIDIM * NDIM];
__device__ __align__(256) __nv_bfloat16 g_Yth[(size_t)BSZ * NDIM * CIDIM];
__device__ __align__(256) __nv_bfloat16 g_Ytl[(size_t)BSZ * NDIM * CIDIM];
__device__ __align__(256) float         g_S  [(size_t)BSZ * NDIM * NDIM];   // fp32 scores
__device__ __align__(256) __nv_bfloat16 g_Ph [(size_t)BSZ * NDIM * NDIM];
__device__ __align__(256) __nv_bfloat16 g_Pl [(size_t)BSZ * NDIM * NDIM];

// ---------------------------------------------------------------------------
__device__ __forceinline__ uint32_t smem_u32(const void* p) {
    uint32_t a;
    asm("{ .reg .u64 t; cvta.to.shared.u64 t, %1; cvt.u32.u64 %0, t; }"
        : "=r"(a) : "l"(p));
    return a;
}

#define LDSM4(rr, addr) \
    asm volatile("ldmatrix.sync.aligned.m8n8.x4.shared.b16 {%0,%1,%2,%3}, [%4];" \
        : "=r"((rr)[0]), "=r"((rr)[1]), "=r"((rr)[2]), "=r"((rr)[3]) : "r"(addr))

#define MMA(dd, aa, b0v, b1v) \
    asm volatile("mma.sync.aligned.m16n8k16.row.col.f32.bf16.bf16.f32 " \
        "{%0,%1,%2,%3}, {%4,%5,%6,%7}, {%8,%9}, {%0,%1,%2,%3};" \
        : "+f"((dd)[0]), "+f"((dd)[1]), "+f"((dd)[2]), "+f"((dd)[3]) \
        : "r"((aa)[0]), "r"((aa)[1]), "r"((aa)[2]), "r"((aa)[3]), \
          "r"(b0v), "r"(b1v))

#define CP16(dst, src) \
    asm volatile("cp.async.cg.shared.global [%0], [%1], 16;" :: "r"(dst), "l"(src))
#define CP_COMMIT() asm volatile("cp.async.commit_group;" ::: "memory")
#define CP_WAIT0()  asm volatile("cp.async.wait_group 0;" ::: "memory")

// SMEM: per stage 4 tiles (Ah, Al, Bh, Bl), each 128 rows x 80B (64B data + pad)
#define ROWB   80u
#define TILEB  (128u * ROWB)     // 10240
#define STAGEB (4u * TILEB)      // 40960
#define SMEMSZ (2u * STAGEB)     // 81920

__device__ __forceinline__ void split2(float a, float b, uint32_t& hi, uint32_t& lo) {
    __nv_bfloat16 ha = __float2bfloat16(a);
    __nv_bfloat16 hb = __float2bfloat16(b);
    __nv_bfloat16 la = __float2bfloat16(a - __bfloat162float(ha));
    __nv_bfloat16 lb = __float2bfloat16(b - __bfloat162float(hb));
    hi = (uint32_t)__bfloat16_as_ushort(ha) | ((uint32_t)__bfloat16_as_ushort(hb) << 16);
    lo = (uint32_t)__bfloat16_as_ushort(la) | ((uint32_t)__bfloat16_as_ushort(lb) << 16);
}

// ---------------------------------------------------------------------------
// Split-bf16 GEMM on pre-split operands:
//   acc[i,j] = sum_k ( Ah*Bh + Ah*Bl + Al*Bh )[i,k][j,k]
// A: M x K (K-major), B: N' x K (K-major), all ld = Kd.
// grid (N'/128, M/128, Z), 256 thr, warp grid 2x4, warp tile 64x32, cp.async x2.
// EPI: 0 = f32 out, scale
//      1 = split out + bias[col], DUAL (z = 2*BSZ: second half uses B2/C2/bias2)
//      2 = split out + bias[row]
//      3 = split out, no bias
//      4 = f32 out + bias[row] + resid
// ---------------------------------------------------------------------------
template <int EPI>
__global__ __launch_bounds__(256, 2)
void tgemm(const __nv_bfloat16* __restrict__ Ah, const __nv_bfloat16* __restrict__ Al,
           const __nv_bfloat16* __restrict__ Bh, const __nv_bfloat16* __restrict__ Bl,
           const __nv_bfloat16* __restrict__ B2h, const __nv_bfloat16* __restrict__ B2l,
           float* __restrict__ Cf,
           __nv_bfloat16* __restrict__ Chi, __nv_bfloat16* __restrict__ Clo,
           __nv_bfloat16* __restrict__ C2hi, __nv_bfloat16* __restrict__ C2lo,
           int Kd, int ldc, size_t aStr, size_t bStr, size_t cStr,
           const float* __restrict__ bias, const float* __restrict__ bias2,
           const float* __restrict__ resid, size_t rStr, float scale)
{
    extern __shared__ __align__(128) char smem[];
    const int tid  = threadIdx.x;
    const int lane = tid & 31;
    const int wid  = tid >> 5;
    const int wm   = wid >> 2;
    const int wn   = wid & 3;

    int batch, sel = 0;
    if (EPI == 1) { batch = blockIdx.z & 1; sel = blockIdx.z >> 1; }
    else          { batch = blockIdx.z; }

    const __nv_bfloat16* Ap  = Ah + (size_t)batch * aStr;
    const __nv_bfloat16* Alp = Al + (size_t)batch * aStr;
    const __nv_bfloat16* Bp  = (EPI == 1 && sel) ? B2h : Bh;
    const __nv_bfloat16* Blp = (EPI == 1 && sel) ? B2l : Bl;
    Bp  += (size_t)batch * bStr;
    Blp += (size_t)batch * bStr;

    const int rowA = blockIdx.y * 128;
    const int rowB = blockIdx.x * 128;
    const uint32_t sb = smem_u32(smem);

    // ldmatrix addresses
    const uint32_t aAddr = sb
        + (uint32_t)(wm * 64 + (lane & 15)) * ROWB + (uint32_t)(lane >> 4) * 16;
    const int bq = lane >> 3;
    const uint32_t bAddr = sb + 2 * TILEB
        + (uint32_t)(wn * 32 + (bq >> 1) * 8 + (lane & 7)) * ROWB
        + (uint32_t)(bq & 1) * 16;

    float d[4][4][4];
    #pragma unroll
    for (int i = 0; i < 4; i++)
        #pragma unroll
        for (int j = 0; j < 4; j++)
            #pragma unroll
            for (int q = 0; q < 4; q++) d[i][j][q] = 0.f;

    const int nk = Kd / 32;

    // per-thread load geometry (fixed): row = idx>>2, 16B-chunk = idx&3
    const int lrow = tid >> 2;
    const int lc8  = (tid & 3) * 8;

    auto LOAD = [&](int kc, int s) {
        const uint32_t so = sb + (uint32_t)s * STAGEB;
        const int k0 = kc * 32 + lc8;
        #pragma unroll
        for (int t = 0; t < 4; t++) {
            const __nv_bfloat16* src =
                (t == 0) ? Ap : (t == 1) ? Alp : (t == 2) ? Bp : Blp;
            const int rb = (t < 2) ? rowA : rowB;
            #pragma unroll
            for (int r = 0; r < 2; r++) {
                const int row = lrow + r * 64;
                const uint32_t dst = so + (uint32_t)t * TILEB
                                   + (uint32_t)row * ROWB + (uint32_t)(lc8 * 2);
                const void* g = src + (size_t)(rb + row) * Kd + k0;
                CP16(dst, g);
            }
        }
        CP_COMMIT();
    };

    // B-fragments resident, A-fragments streamed per mi (low reg pressure)
    auto COMPUTE = [&](int s) {
        const uint32_t so = (uint32_t)s * STAGEB;
        #pragma unroll
        for (int ks = 0; ks < 2; ks++) {
            const uint32_t ab = aAddr + so + ks * 32;
            const uint32_t bb = bAddr + so + ks * 32;
            uint32_t bh[2][4], bl[2][4];
            #pragma unroll
            for (int np = 0; np < 2; np++) {
                LDSM4(bh[np], bb + np * 16 * ROWB);
                LDSM4(bl[np], bb + TILEB + np * 16 * ROWB);
            }
            #pragma unroll
            for (int mi = 0; mi < 4; mi++) {
                uint32_t ah[4], al[4];
                LDSM4(ah, ab + mi * 16 * ROWB);
                LDSM4(al, ab + TILEB + mi * 16 * ROWB);
                #pragma unroll
                for (int ni = 0; ni < 4; ni++) {
                    const int np = ni >> 1, h = (ni & 1) * 2;
                    MMA(d[mi][ni], ah, bh[np][h], bh[np][h + 1]);
                    MMA(d[mi][ni], ah, bl[np][h], bl[np][h + 1]);
                    MMA(d[mi][ni], al, bh[np][h], bh[np][h + 1]);
                }
            }
        }
    };

    // Single-barrier pipeline: the top-of-iteration barrier proves everyone
    // finished computing on the slot that LOAD(c+1) will overwrite.
    LOAD(0, 0);
    for (int c = 0; c < nk; c++) {
        const int s = c & 1;
        CP_WAIT0();
        __syncthreads();
        if (c + 1 < nk) LOAD(c + 1, s ^ 1);
        COMPUTE(s);
    }

    // ---- epilogue ----
    float* Cfp = (EPI == 0 || EPI == 4) ? (Cf + (size_t)batch * cStr) : nullptr;
    __nv_bfloat16* Ch = nullptr; __nv_bfloat16* Cl = nullptr;
    if (EPI == 1 || EPI == 2 || EPI == 3) {
        Ch = ((EPI == 1 && sel) ? C2hi : Chi) + (size_t)batch * cStr;
        Cl = ((EPI == 1 && sel) ? C2lo : Clo) + (size_t)batch * cStr;
    }
    const float* bp = (EPI == 1 && sel) ? bias2 : bias;

    const int r0base = rowA + wm * 64;
    const int c0base = rowB + wn * 32;
    #pragma unroll
    for (int mi = 0; mi < 4; mi++) {
        const int row0 = r0base + mi * 16 + (lane >> 2);
        const int row1 = row0 + 8;
        float bi0 = 0.f, bi1 = 0.f;
        if (EPI == 2 || EPI == 4) { bi0 = bp[row0]; bi1 = bp[row1]; }
        #pragma unroll
        for (int ni = 0; ni < 4; ni++) {
            const int col = c0base + ni * 8 + (lane & 3) * 2;
            float v00 = d[mi][ni][0] * scale, v01 = d[mi][ni][1] * scale;
            float v10 = d[mi][ni][2] * scale, v11 = d[mi][ni][3] * scale;
            if (EPI == 1) {
                float b0 = bp[col], b1 = bp[col + 1];
                v00 += b0; v01 += b1; v10 += b0; v11 += b1;
            }
            if (EPI == 2 || EPI == 4) { v00 += bi0; v01 += bi0; v10 += bi1; v11 += bi1; }
            if (EPI == 4) {
                const float* rb = resid + (size_t)batch * rStr;
                float2 q0 = *(const float2*)(rb + (size_t)row0 * ldc + col);
                float2 q1 = *(const float2*)(rb + (size_t)row1 * ldc + col);
                v00 += q0.x; v01 += q0.y; v10 += q1.x; v11 += q1.y;
            }
            if (EPI == 0 || EPI == 4) {
                *(float2*)(Cfp + (size_t)row0 * ldc + col) = make_float2(v00, v01);
                *(float2*)(Cfp + (size_t)row1 * ldc + col) = make_float2(v10, v11);
            } else {
                uint32_t h0, l0, h1, l1;
                split2(v00, v01, h0, l0);
                split2(v10, v11, h1, l1);
                *(uint32_t*)(Ch + (size_t)row0 * ldc + col) = h0;
                *(uint32_t*)(Cl + (size_t)row0 * ldc + col) = l0;
                *(uint32_t*)(Ch + (size_t)row1 * ldc + col) = h1;
                *(uint32_t*)(Cl + (size_t)row1 * ldc + col) = l1;
            }
        }
    }
}

// ---------------------------------------------------------------------------
// 32x32 tiled transpose + split: x (B,C,N) fp32 -> xT hi/lo (B,N,C) bf16
// ---------------------------------------------------------------------------
__global__ __launch_bounds__(256)
void transpose_split(const float* __restrict__ src,
                     __nv_bfloat16* __restrict__ dh, __nv_bfloat16* __restrict__ dl)
{
    __shared__ float t[32][33];
    const float* s = src + (size_t)blockIdx.z * CDIM * NDIM;
    __nv_bfloat16* oh = dh + (size_t)blockIdx.z * NDIM * CDIM;
    __nv_bfloat16* ol = dl + (size_t)blockIdx.z * NDIM * CDIM;
    const int n0 = blockIdx.x * 32;
    const int c0 = blockIdx.y * 32;
    const int tx = threadIdx.x, ty = threadIdx.y;
    #pragma unroll
    for (int r = 0; r < 4; r++)
        t[ty + r * 8][tx] = s[(size_t)(c0 + ty + r * 8) * NDIM + n0 + tx];
    __syncthreads();
    #pragma unroll
    for (int r = 0; r < 4; r++) {
        float v = t[tx][ty + r * 8];
        __nv_bfloat16 h = __float2bfloat16(v);
        __nv_bfloat16 l = __float2bfloat16(v - __bfloat162float(h));
        const size_t o = (size_t)(n0 + ty + r * 8) * CDIM + c0 + tx;
        oh[o] = h; ol[o] = l;
    }
}

// Elementwise fp32 -> bf16 hi/lo split (weights), vectorized x4
__global__ __launch_bounds__(256)
void split_mat(const float* __restrict__ src,
               __nv_bfloat16* __restrict__ dh, __nv_bfloat16* __restrict__ dl, int n4)
{
    const int i = blockIdx.x * 256 + threadIdx.x;
    if (i >= n4) return;
    float4 v = ((const float4*)src)[i];
    uint32_t h0, l0, h1, l1;
    split2(v.x, v.y, h0, l0);
    split2(v.z, v.w, h1, l1);
    ((uint2*)dh)[i] = make_uint2(h0, h1);
    ((uint2*)dl)[i] = make_uint2(l0, l1);
}

// ---------------------------------------------------------------------------
// Row softmax (fp32 in) -> probability hi/lo bf16 out
// ---------------------------------------------------------------------------
#define SM_VPT 25
__global__ __launch_bounds__(256)
void softmax_split(const float* __restrict__ S,
                   __nv_bfloat16* __restrict__ Ph, __nv_bfloat16* __restrict__ Pl, int n)
{
    const float* row = S + (size_t)blockIdx.x * n;
    __nv_bfloat16* ph = Ph + (size_t)blockIdx.x * n;
    __nv_bfloat16* pl = Pl + (size_t)blockIdx.x * n;
    const int t = threadIdx.x;
    __shared__ float red[256];

    float vals[SM_VPT];
    float mx = -3.402823466e38f;
    #pragma unroll
    for (int v = 0; v < SM_VPT; v++) {
        int j = v * 256 + t;
        if (j < n) { vals[v] = row[j]; mx = fmaxf(mx, vals[v]); }
        else vals[v] = -3.402823466e38f;
    }
    red[t] = mx; __syncthreads();
    for (int s = 128; s > 0; s >>= 1) {
        if (t < s) red[t] = fmaxf(red[t], red[t + s]);
        __syncthreads();
    }
    mx = red[0];
    __syncthreads();

    float sum = 0.f;
    #pragma unroll
    for (int v = 0; v < SM_VPT; v++) {
        int j = v * 256 + t;
        if (j < n) { vals[v] = __expf(vals[v] - mx); sum += vals[v]; }
    }
    red[t] = sum; __syncthreads();
    for (int s = 128; s > 0; s >>= 1) {
        if (t < s) red[t] += red[t + s];
        __syncthreads();
    }
    const float inv = 1.f / red[0];

    #pragma unroll
    for (int v = 0; v < SM_VPT; v++) {
        int j = v * 256 + t;
        if (j < n) {
            float p = vals[v] * inv;
            __nv_bfloat16 h = __float2bfloat16(p);
            ph[j] = h;
            pl[j] = __float2bfloat16(p - __bfloat162float(h));
        }
    }
}

// ---------------------------------------------------------------------------
extern "C" void kernel_launch(void* const* d_in, const int* in_sizes, int n_in,
                              void* d_out, int out_size)
{
    const float* x  = (const float*)d_in[0];   // (B, C, N)
    const float* Wk = (const float*)d_in[1];   // (CI, C)
    const float* bk = (const float*)d_in[2];
    const float* Wq = (const float*)d_in[3];
    const float* bq = (const float*)d_in[4];
    const float* Wv = (const float*)d_in[5];
    const float* bv = (const float*)d_in[6];
    const float* Wo = (const float*)d_in[7];   // (C, CI)
    const float* bo = (const float*)d_in[8];
    float* out = (float*)d_out;                // (B, C, N)

    __nv_bfloat16 *xTh, *xTl, *Wkh, *Wkl, *Wqh, *Wql, *Wvh, *Wvl, *Woh, *Wol;
    __nv_bfloat16 *Kth, *Ktl, *Qth, *Qtl, *Vh, *Vl, *Yth, *Ytl, *Ph, *Pl;
    float* S;
    cudaGetSymbolAddress((void**)&xTh, g_xTh); cudaGetSymbolAddress((void**)&xTl, g_xTl);
    cudaGetSymbolAddress((void**)&Wkh, g_Wkh); cudaGetSymbolAddress((void**)&Wkl, g_Wkl);
    cudaGetSymbolAddress((void**)&Wqh, g_Wqh); cudaGetSymbolAddress((void**)&Wql, g_Wql);
    cudaGetSymbolAddress((void**)&Wvh, g_Wvh); cudaGetSymbolAddress((void**)&Wvl, g_Wvl);
    cudaGetSymbolAddress((void**)&Woh, g_Woh); cudaGetSymbolAddress((void**)&Wol, g_Wol);
    cudaGetSymbolAddress((void**)&Kth, g_Kth); cudaGetSymbolAddress((void**)&Ktl, g_Ktl);
    cudaGetSymbolAddress((void**)&Qth, g_Qth); cudaGetSymbolAddress((void**)&Qtl, g_Qtl);
    cudaGetSymbolAddress((void**)&Vh,  g_Vh);  cudaGetSymbolAddress((void**)&Vl,  g_Vl);
    cudaGetSymbolAddress((void**)&Yth, g_Yth); cudaGetSymbolAddress((void**)&Ytl, g_Ytl);
    cudaGetSymbolAddress((void**)&Ph,  g_Ph);  cudaGetSymbolAddress((void**)&Pl,  g_Pl);
    cudaGetSymbolAddress((void**)&S,   g_S);

    cudaFuncSetAttribute(tgemm<0>, cudaFuncAttributeMaxDynamicSharedMemorySize, SMEMSZ);
    cudaFuncSetAttribute(tgemm<1>, cudaFuncAttributeMaxDynamicSharedMemorySize, SMEMSZ);
    cudaFuncSetAttribute(tgemm<2>, cudaFuncAttributeMaxDynamicSharedMemorySize, SMEMSZ);
    cudaFuncSetAttribute(tgemm<3>, cudaFuncAttributeMaxDynamicSharedMemorySize, SMEMSZ);
    cudaFuncSetAttribute(tgemm<4>, cudaFuncAttributeMaxDynamicSharedMemorySize, SMEMSZ);

    const size_t pstr = (size_t)NDIM * CIDIM;   // Kt/Qt/Yt batch stride (elems)
    const size_t vstr = (size_t)CIDIM * NDIM;   // V batch stride
    const size_t xstr = (size_t)CDIM * NDIM;    // x/out batch stride
    const size_t tstr = (size_t)NDIM * CDIM;    // xT batch stride
    const size_t sstr = (size_t)NDIM * NDIM;    // S/P batch stride

    const int w4 = (CIDIM * CDIM) / 4;          // all weight mats same elem count

    // 0) splits
    transpose_split<<<dim3(NDIM / 32, CDIM / 32, BSZ), dim3(32, 8)>>>(x, xTh, xTl);
    split_mat<<<(w4 + 255) / 256, 256>>>(Wk, Wkh, Wkl, w4);
    split_mat<<<(w4 + 255) / 256, 256>>>(Wq, Wqh, Wql, w4);
    split_mat<<<(w4 + 255) / 256, 256>>>(Wv, Wvh, Wvl, w4);
    split_mat<<<(w4 + 255) / 256, 256>>>(Wo, Woh, Wol, w4);

    // 1) K & Q projections (merged, DUAL): Kt/Qt[n,d] = xT[n,:]·W[d,:] + b[d]
    tgemm<1><<<dim3(CIDIM / 128, NDIM / 128, 2 * BSZ), 256, SMEMSZ>>>(
        xTh, xTl, Wkh, Wkl, Wqh, Wql,
        nullptr, Kth, Ktl, Qth, Qtl,
        CDIM, CIDIM, tstr, 0, pstr, bk, bq, nullptr, 0, 1.0f);

    // 2) V[c,n] = Wv[c,:]·xT[n,:] + bv[c]
    tgemm<2><<<dim3(NDIM / 128, CIDIM / 128, BSZ), 256, SMEMSZ>>>(
        Wvh, Wvl, xTh, xTl, nullptr, nullptr,
        nullptr, Vh, Vl, nullptr, nullptr,
        CDIM, NDIM, 0, tstr, vstr, bv, nullptr, nullptr, 0, 1.0f);

    // 3) S[i,j] = (1/T) Kt[i,:]·Qt[j,:]  (fp32 out)
    tgemm<0><<<dim3(NDIM / 128, NDIM / 128, BSZ), 256, SMEMSZ>>>(
        Kth, Ktl, Qth, Qtl, nullptr, nullptr,
        S, nullptr, nullptr, nullptr, nullptr,
        CIDIM, NDIM, pstr, pstr, sstr, nullptr, nullptr, nullptr, 0,
        1.0f / (float)TDIM);

    // 4) softmax -> P hi/lo
    softmax_split<<<BSZ * NDIM, 256>>>(S, Ph, Pl, NDIM);

    // 5) Yt[i,c] = P[i,:]·V[c,:]
    tgemm<3><<<dim3(CIDIM / 128, NDIM / 128, BSZ), 256, SMEMSZ>>>(
        Ph, Pl, Vh, Vl, nullptr, nullptr,
        nullptr, Yth, Ytl, nullptr, nullptr,
        NDIM, CIDIM, sstr, vstr, pstr, nullptr, nullptr, nullptr, 0, 1.0f);

    // 6) out[c,n] = Wo[c,:]·Yt[n,:] + bo[c] + x[c,n]  (fp32 out)
    tgemm<4><<<dim3(NDIM / 128, CDIM / 128, BSZ), 256, SMEMSZ>>>(
        Woh, Wol, Yth, Ytl, nullptr, nullptr,
        out, nullptr, nullptr, nullptr, nullptr,
        CIDIM, NDIM, 0, pstr, xstr, bo, nullptr, x, xstr, 1.0f);
}

// round 7
// speedup vs baseline: 3.2420x; 1.0076x over previous
#include <cuda_runtime.h>
#include <cuda_bf16.h>
#include <cstdint>

// Problem constants
#define BSZ   2
#define CDIM  1024
#define CIDIM 512
#define NDIM  6272     // 32*14*14 = 49*128
#define NHALF 3136     // NDIM/2 (split-K for alpha*V)
#define TDIM  32

// bf16 hi/lo scratch (allocation-free rule: __device__ globals)
__device__ __align__(256) __nv_bfloat16 g_xTh[(size_t)BSZ * NDIM * CDIM];
__device__ __align__(256) __nv_bfloat16 g_xTl[(size_t)BSZ * NDIM * CDIM];
__device__ __align__(256) __nv_bfloat16 g_Wkh[CIDIM * CDIM];
__device__ __align__(256) __nv_bfloat16 g_Wkl[CIDIM * CDIM];
__device__ __align__(256) __nv_bfloat16 g_Wqh[CIDIM * CDIM];
__device__ __align__(256) __nv_bfloat16 g_Wql[CIDIM * CDIM];
__device__ __align__(256) __nv_bfloat16 g_Wvh[CIDIM * CDIM];
__device__ __align__(256) __nv_bfloat16 g_Wvl[CIDIM * CDIM];
__device__ __align__(256) __nv_bfloat16 g_Woh[CDIM * CIDIM];
__device__ __align__(256) __nv_bfloat16 g_Wol[CDIM * CIDIM];
__device__ __align__(256) __nv_bfloat16 g_Kth[(size_t)BSZ * NDIM * CIDIM];
__device__ __align__(256) __nv_bfloat16 g_Ktl[(size_t)BSZ * NDIM * CIDIM];
__device__ __align__(256) __nv_bfloat16 g_Qth[(size_t)BSZ * NDIM * CIDIM];
__device__ __align__(256) __nv_bfloat16 g_Qtl[(size_t)BSZ * NDIM * CIDIM];
__device__ __align__(256) __nv_bfloat16 g_Vth[(size_t)BSZ * NDIM * CIDIM];  // V^T [n,c]
__device__ __align__(256) __nv_bfloat16 g_Vtl[(size_t)BSZ * NDIM * CIDIM];
__device__ __align__(256) __nv_bfloat16 g_Vh [(size_t)BSZ * CIDIM * NDIM]; // V [c,n]
__device__ __align__(256) __nv_bfloat16 g_Vl [(size_t)BSZ * CIDIM * NDIM];
__device__ __align__(256) __nv_bfloat16 g_Yth[(size_t)BSZ * NDIM * CIDIM];
__device__ __align__(256) __nv_bfloat16 g_Ytl[(size_t)BSZ * NDIM * CIDIM];
__device__ __align__(256) float         g_S  [(size_t)BSZ * NDIM * NDIM];  // scores; later Y partials
__device__ __align__(256) __nv_bfloat16 g_Ph [(size_t)BSZ * NDIM * NDIM];
__device__ __align__(256) __nv_bfloat16 g_Pl [(size_t)BSZ * NDIM * NDIM];

// ---------------------------------------------------------------------------
__device__ __forceinline__ uint32_t smem_u32(const void* p) {
    uint32_t a;
    asm("{ .reg .u64 t; cvta.to.shared.u64 t, %1; cvt.u32.u64 %0, t; }"
        : "=r"(a) : "l"(p));
    return a;
}

#define LDSM4(rr, addr) \
    asm volatile("ldmatrix.sync.aligned.m8n8.x4.shared.b16 {%0,%1,%2,%3}, [%4];" \
        : "=r"((rr)[0]), "=r"((rr)[1]), "=r"((rr)[2]), "=r"((rr)[3]) : "r"(addr))

#define MMA(dd, aa, b0v, b1v) \
    asm volatile("mma.sync.aligned.m16n8k16.row.col.f32.bf16.bf16.f32 " \
        "{%0,%1,%2,%3}, {%4,%5,%6,%7}, {%8,%9}, {%0,%1,%2,%3};" \
        : "+f"((dd)[0]), "+f"((dd)[1]), "+f"((dd)[2]), "+f"((dd)[3]) \
        : "r"((aa)[0]), "r"((aa)[1]), "r"((aa)[2]), "r"((aa)[3]), \
          "r"(b0v), "r"(b1v))

#define CP16(dst, src) \
    asm volatile("cp.async.cg.shared.global [%0], [%1], 16;" :: "r"(dst), "l"(src))
#define CP_COMMIT() asm volatile("cp.async.commit_group;" ::: "memory")
#define CP_WAIT0()  asm volatile("cp.async.wait_group 0;" ::: "memory")

// SMEM: per stage 4 tiles (Ah, Al, Bh, Bl), each 128 rows x 80B (64B data + pad)
#define ROWB   80u
#define TILEB  (128u * ROWB)     // 10240
#define STAGEB (4u * TILEB)     // 40960
#define SMEMSZ (2u * STAGEB)    // 81920

__device__ __forceinline__ void split2(float a, float b, uint32_t& hi, uint32_t& lo) {
    __nv_bfloat16 ha = __float2bfloat16(a);
    __nv_bfloat16 hb = __float2bfloat16(b);
    __nv_bfloat16 la = __float2bfloat16(a - __bfloat162float(ha));
    __nv_bfloat16 lb = __float2bfloat16(b - __bfloat162float(hb));
    hi = (uint32_t)__bfloat16_as_ushort(ha) | ((uint32_t)__bfloat16_as_ushort(hb) << 16);
    lo = (uint32_t)__bfloat16_as_ushort(la) | ((uint32_t)__bfloat16_as_ushort(lb) << 16);
}

// ---------------------------------------------------------------------------
// Split-bf16 GEMM on pre-split operands:
//   acc[i,j] = sum_k ( Ah*Bh + Ah*Bl + Al*Bh )[i,k][j,k]
// A: M x K (K-major, ld=ldab), B: N' x K (K-major, ld=ldab for EPI5, else Kd)
// EPI: 0 = f32 out, scale                 (scores; grid z = batch)
//      1 = TRIPLE split out + bias[col]   (KQV proj; z = batch + 2*sel, sel 0..2)
//      4 = f32 out + bias[row] + resid    (out proj; z = batch)
//      5 = split-K f32 partial out        (alphaV; z = batch + 2*kh, kh 0..1)
// ---------------------------------------------------------------------------
template <int EPI>
__global__ __launch_bounds__(256, 2)
void tgemm(const __nv_bfloat16* __restrict__ Ah, const __nv_bfloat16* __restrict__ Al,
           const __nv_bfloat16* __restrict__ B0h, const __nv_bfloat16* __restrict__ B0l,
           const __nv_bfloat16* __restrict__ B1h, const __nv_bfloat16* __restrict__ B1l,
           const __nv_bfloat16* __restrict__ B2h, const __nv_bfloat16* __restrict__ B2l,
           float* __restrict__ Cf,
           __nv_bfloat16* __restrict__ C0h, __nv_bfloat16* __restrict__ C0l,
           __nv_bfloat16* __restrict__ C1h, __nv_bfloat16* __restrict__ C1l,
           __nv_bfloat16* __restrict__ C2h, __nv_bfloat16* __restrict__ C2l,
           int Kd, int ldab, int ldc,
           size_t aStr, size_t bStr, size_t cStr, size_t khStr,
           const float* __restrict__ bias0, const float* __restrict__ bias1,
           const float* __restrict__ bias2,
           const float* __restrict__ resid, size_t rStr, float scale)
{
    extern __shared__ __align__(128) char smem[];
    const int tid  = threadIdx.x;
    const int lane = tid & 31;
    const int wid  = tid >> 5;
    const int wm   = wid >> 2;
    const int wn   = wid & 3;

    const int batch = blockIdx.z & 1;
    const int sel   = blockIdx.z >> 1;    // EPI1: which W; EPI5: which K-half; else 0

    const __nv_bfloat16* Ap  = Ah + (size_t)batch * aStr;
    const __nv_bfloat16* Alp = Al + (size_t)batch * aStr;
    const __nv_bfloat16* Bp;
    const __nv_bfloat16* Blp;
    if (EPI == 1) {
        Bp  = (sel == 0) ? B0h : (sel == 1) ? B1h : B2h;
        Blp = (sel == 0) ? B0l : (sel == 1) ? B1l : B2l;
    } else { Bp = B0h; Blp = B0l; }
    Bp  += (size_t)batch * bStr;
    Blp += (size_t)batch * bStr;
    if (EPI == 5) {                         // split-K column offset
        const int koff = sel * NHALF;
        Ap += koff; Alp += koff; Bp += koff; Blp += koff;
    }

    const int rowA = blockIdx.y * 128;
    const int rowB = blockIdx.x * 128;
    const uint32_t sb = smem_u32(smem);

    // ldmatrix addresses
    const uint32_t aAddr = sb
        + (uint32_t)(wm * 64 + (lane & 15)) * ROWB + (uint32_t)(lane >> 4) * 16;
    const int bq = lane >> 3;
    const uint32_t bAddr = sb + 2 * TILEB
        + (uint32_t)(wn * 32 + (bq >> 1) * 8 + (lane & 7)) * ROWB
        + (uint32_t)(bq & 1) * 16;

    float d[4][4][4];
    #pragma unroll
    for (int i = 0; i < 4; i++)
        #pragma unroll
        for (int j = 0; j < 4; j++)
            #pragma unroll
            for (int q = 0; q < 4; q++) d[i][j][q] = 0.f;

    const int nk = Kd / 32;
    const int lrow = tid >> 2;
    const int lc8  = (tid & 3) * 8;

    auto LOAD = [&](int kc, int s) {
        const uint32_t so = sb + (uint32_t)s * STAGEB;
        const int k0 = kc * 32 + lc8;
        #pragma unroll
        for (int t = 0; t < 4; t++) {
            const __nv_bfloat16* src =
                (t == 0) ? Ap : (t == 1) ? Alp : (t == 2) ? Bp : Blp;
            const int rb = (t < 2) ? rowA : rowB;
            #pragma unroll
            for (int r = 0; r < 2; r++) {
                const int row = lrow + r * 64;
                const uint32_t dst = so + (uint32_t)t * TILEB
                                   + (uint32_t)row * ROWB + (uint32_t)(lc8 * 2);
                const void* g = src + (size_t)(rb + row) * ldab + k0;
                CP16(dst, g);
            }
        }
        CP_COMMIT();
    };

    auto COMPUTE = [&](int s) {
        const uint32_t so = (uint32_t)s * STAGEB;
        #pragma unroll
        for (int ks = 0; ks < 2; ks++) {
            const uint32_t ab = aAddr + so + ks * 32;
            const uint32_t bb = bAddr + so + ks * 32;
            uint32_t bh[2][4], bl[2][4];
            #pragma unroll
            for (int np = 0; np < 2; np++) {
                LDSM4(bh[np], bb + np * 16 * ROWB);
                LDSM4(bl[np], bb + TILEB + np * 16 * ROWB);
            }
            #pragma unroll
            for (int mi = 0; mi < 4; mi++) {
                uint32_t ah[4], al[4];
                LDSM4(ah, ab + mi * 16 * ROWB);
                LDSM4(al, ab + TILEB + mi * 16 * ROWB);
                #pragma unroll
                for (int ni = 0; ni < 4; ni++) {
                    const int np = ni >> 1, h = (ni & 1) * 2;
                    MMA(d[mi][ni], ah, bh[np][h], bh[np][h + 1]);
                    MMA(d[mi][ni], ah, bl[np][h], bl[np][h + 1]);
                    MMA(d[mi][ni], al, bh[np][h], bh[np][h + 1]);
                }
            }
        }
    };

    LOAD(0, 0);
    for (int c = 0; c < nk; c++) {
        const int s = c & 1;
        CP_WAIT0();
        __syncthreads();
        if (c + 1 < nk) LOAD(c + 1, s ^ 1);
        COMPUTE(s);
    }

    // ---- epilogue ----
    float* Cfp = nullptr;
    __nv_bfloat16* Ch = nullptr; __nv_bfloat16* Cl = nullptr;
    if (EPI == 0 || EPI == 4) Cfp = Cf + (size_t)batch * cStr;
    if (EPI == 5)             Cfp = Cf + (size_t)batch * cStr + (size_t)sel * khStr;
    if (EPI == 1) {
        Ch = ((sel == 0) ? C0h : (sel == 1) ? C1h : C2h) + (size_t)batch * cStr;
        Cl = ((sel == 0) ? C0l : (sel == 1) ? C1l : C2l) + (size_t)batch * cStr;
    }
    const float* bp = (EPI == 1)
        ? ((sel == 0) ? bias0 : (sel == 1) ? bias1 : bias2) : bias0;

    const int r0base = rowA + wm * 64;
    const int c0base = rowB + wn * 32;
    #pragma unroll
    for (int mi = 0; mi < 4; mi++) {
        const int row0 = r0base + mi * 16 + (lane >> 2);
        const int row1 = row0 + 8;
        float bi0 = 0.f, bi1 = 0.f;
        if (EPI == 4) { bi0 = bp[row0]; bi1 = bp[row1]; }
        #pragma unroll
        for (int ni = 0; ni < 4; ni++) {
            const int col = c0base + ni * 8 + (lane & 3) * 2;
            float v00 = d[mi][ni][0] * scale, v01 = d[mi][ni][1] * scale;
            float v10 = d[mi][ni][2] * scale, v11 = d[mi][ni][3] * scale;
            if (EPI == 1) {
                float b0 = bp[col], b1 = bp[col + 1];
                v00 += b0; v01 += b1; v10 += b0; v11 += b1;
            }
            if (EPI == 4) {
                v00 += bi0; v01 += bi0; v10 += bi1; v11 += bi1;
                const float* rb = resid + (size_t)batch * rStr;
                float2 q0 = *(const float2*)(rb + (size_t)row0 * ldc + col);
                float2 q1 = *(const float2*)(rb + (size_t)row1 * ldc + col);
                v00 += q0.x; v01 += q0.y; v10 += q1.x; v11 += q1.y;
            }
            if (EPI == 0 || EPI == 4 || EPI == 5) {
                *(float2*)(Cfp + (size_t)row0 * ldc + col) = make_float2(v00, v01);
                *(float2*)(Cfp + (size_t)row1 * ldc + col) = make_float2(v10, v11);
            } else {
                uint32_t h0, l0, h1, l1;
                split2(v00, v01, h0, l0);
                split2(v10, v11, h1, l1);
                *(uint32_t*)(Ch + (size_t)row0 * ldc + col) = h0;
                *(uint32_t*)(Cl + (size_t)row0 * ldc + col) = l0;
                *(uint32_t*)(Ch + (size_t)row1 * ldc + col) = h1;
                *(uint32_t*)(Cl + (size_t)row1 * ldc + col) = l1;
            }
        }
    }
}

// ---------------------------------------------------------------------------
// 32x32 tiled transpose + split: x (B,C,N) fp32 -> xT hi/lo (B,N,C) bf16
// ---------------------------------------------------------------------------
__global__ __launch_bounds__(256)
void transpose_split(const float* __restrict__ src,
                     __nv_bfloat16* __restrict__ dh, __nv_bfloat16* __restrict__ dl)
{
    __shared__ float t[32][33];
    const float* s = src + (size_t)blockIdx.z * CDIM * NDIM;
    __nv_bfloat16* oh = dh + (size_t)blockIdx.z * NDIM * CDIM;
    __nv_bfloat16* ol = dl + (size_t)blockIdx.z * NDIM * CDIM;
    const int n0 = blockIdx.x * 32;
    const int c0 = blockIdx.y * 32;
    const int tx = threadIdx.x, ty = threadIdx.y;
    #pragma unroll
    for (int r = 0; r < 4; r++)
        t[ty + r * 8][tx] = s[(size_t)(c0 + ty + r * 8) * NDIM + n0 + tx];
    __syncthreads();
    #pragma unroll
    for (int r = 0; r < 4; r++) {
        float v = t[tx][ty + r * 8];
        __nv_bfloat16 h = __float2bfloat16(v);
        __nv_bfloat16 l = __float2bfloat16(v - __bfloat162float(h));
        const size_t o = (size_t)(n0 + ty + r * 8) * CDIM + c0 + tx;
        oh[o] = h; ol[o] = l;
    }
}

// 32x32 bf16 pair transpose: Vt (B,N,CI) -> V (B,CI,N), hi+lo together
__global__ __launch_bounds__(256)
void transpose_v(const __nv_bfloat16* __restrict__ sh, const __nv_bfloat16* __restrict__ sl,
                 __nv_bfloat16* __restrict__ dh, __nv_bfloat16* __restrict__ dl)
{
    __shared__ ushort th[32][33];
    __shared__ ushort tl[32][33];
    const size_t bo = (size_t)blockIdx.z * NDIM * CIDIM;
    const int n0 = blockIdx.x * 32;
    const int c0 = blockIdx.y * 32;
    const int tx = threadIdx.x, ty = threadIdx.y;
    #pragma unroll
    for (int r = 0; r < 4; r++) {
        const size_t i = bo + (size_t)(n0 + ty + r * 8) * CIDIM + c0 + tx;
        th[ty + r * 8][tx] = __bfloat16_as_ushort(sh[i]);
        tl[ty + r * 8][tx] = __bfloat16_as_ushort(sl[i]);
    }
    __syncthreads();
    #pragma unroll
    for (int r = 0; r < 4; r++) {
        const size_t o = bo + (size_t)(c0 + ty + r * 8) * NDIM + n0 + tx;
        dh[o] = __ushort_as_bfloat16(th[tx][ty + r * 8]);
        dl[o] = __ushort_as_bfloat16(tl[tx][ty + r * 8]);
    }
}

// Elementwise fp32 -> bf16 hi/lo split (weights), vectorized x4
__global__ __launch_bounds__(256)
void split_mat(const float* __restrict__ src,
               __nv_bfloat16* __restrict__ dh, __nv_bfloat16* __restrict__ dl, int n4)
{
    const int i = blockIdx.x * 256 + threadIdx.x;
    if (i >= n4) return;
    float4 v = ((const float4*)src)[i];
    uint32_t h0, l0, h1, l1;
    split2(v.x, v.y, h0, l0);
    split2(v.z, v.w, h1, l1);
    ((uint2*)dh)[i] = make_uint2(h0, h1);
    ((uint2*)dl)[i] = make_uint2(l0, l1);
}

// Combine split-K partials (y0 + y1) -> bf16 hi/lo
__global__ __launch_bounds__(256)
void combine_split(const float* __restrict__ y0, const float* __restrict__ y1,
                   __nv_bfloat16* __restrict__ dh, __nv_bfloat16* __restrict__ dl, int n4)
{
    const int i = blockIdx.x * 256 + threadIdx.x;
    if (i >= n4) return;
    float4 a = ((const float4*)y0)[i];
    float4 b = ((const float4*)y1)[i];
    a.x += b.x; a.y += b.y; a.z += b.z; a.w += b.w;
    uint32_t h0, l0, h1, l1;
    split2(a.x, a.y, h0, l0);
    split2(a.z, a.w, h1, l1);
    ((uint2*)dh)[i] = make_uint2(h0, h1);
    ((uint2*)dl)[i] = make_uint2(l0, l1);
}

// ---------------------------------------------------------------------------
// Row softmax (fp32 in) -> probability hi/lo bf16 out
// ---------------------------------------------------------------------------
#define SM_VPT 25
__global__ __launch_bounds__(256)
void softmax_split(const float* __restrict__ S,
                   __nv_bfloat16* __restrict__ Ph, __nv_bfloat16* __restrict__ Pl, int n)
{
    const float* row = S + (size_t)blockIdx.x * n;
    __nv_bfloat16* ph = Ph + (size_t)blockIdx.x * n;
    __nv_bfloat16* pl = Pl + (size_t)blockIdx.x * n;
    const int t = threadIdx.x;
    __shared__ float red[256];

    float vals[SM_VPT];
    float mx = -3.402823466e38f;
    #pragma unroll
    for (int v = 0; v < SM_VPT; v++) {
        int j = v * 256 + t;
        if (j < n) { vals[v] = row[j]; mx = fmaxf(mx, vals[v]); }
        else vals[v] = -3.402823466e38f;
    }
    red[t] = mx; __syncthreads();
    for (int s = 128; s > 0; s >>= 1) {
        if (t < s) red[t] = fmaxf(red[t], red[t + s]);
        __syncthreads();
    }
    mx = red[0];
    __syncthreads();

    float sum = 0.f;
    #pragma unroll
    for (int v = 0; v < SM_VPT; v++) {
        int j = v * 256 + t;
        if (j < n) { vals[v] = __expf(vals[v] - mx); sum += vals[v]; }
    }
    red[t] = sum; __syncthreads();
    for (int s = 128; s > 0; s >>= 1) {
        if (t < s) red[t] += red[t + s];
        __syncthreads();
    }
    const float inv = 1.f / red[0];

    #pragma unroll
    for (int v = 0; v < SM_VPT; v++) {
        int j = v * 256 + t;
        if (j < n) {
            float p = vals[v] * inv;
            __nv_bfloat16 h = __float2bfloat16(p);
            ph[j] = h;
            pl[j] = __float2bfloat16(p - __bfloat162float(h));
        }
    }
}

// ---------------------------------------------------------------------------
extern "C" void kernel_launch(void* const* d_in, const int* in_sizes, int n_in,
                              void* d_out, int out_size)
{
    const float* x  = (const float*)d_in[0];   // (B, C, N)
    const float* Wk = (const float*)d_in[1];   // (CI, C)
    const float* bk = (const float*)d_in[2];
    const float* Wq = (const float*)d_in[3];
    const float* bq = (const float*)d_in[4];
    const float* Wv = (const float*)d_in[5];
    const float* bv = (const float*)d_in[6];
    const float* Wo = (const float*)d_in[7];   // (C, CI)
    const float* bo = (const float*)d_in[8];
    float* out = (float*)d_out;                // (B, C, N)

    __nv_bfloat16 *xTh, *xTl, *Wkh, *Wkl, *Wqh, *Wql, *Wvh, *Wvl, *Woh, *Wol;
    __nv_bfloat16 *Kth, *Ktl, *Qth, *Qtl, *Vth, *Vtl, *Vh, *Vl, *Yth, *Ytl, *Ph, *Pl;
    float* S;
    cudaGetSymbolAddress((void**)&xTh, g_xTh); cudaGetSymbolAddress((void**)&xTl, g_xTl);
    cudaGetSymbolAddress((void**)&Wkh, g_Wkh); cudaGetSymbolAddress((void**)&Wkl, g_Wkl);
    cudaGetSymbolAddress((void**)&Wqh, g_Wqh); cudaGetSymbolAddress((void**)&Wql, g_Wql);
    cudaGetSymbolAddress((void**)&Wvh, g_Wvh); cudaGetSymbolAddress((void**)&Wvl, g_Wvl);
    cudaGetSymbolAddress((void**)&Woh, g_Woh); cudaGetSymbolAddress((void**)&Wol, g_Wol);
    cudaGetSymbolAddress((void**)&Kth, g_Kth); cudaGetSymbolAddress((void**)&Ktl, g_Ktl);
    cudaGetSymbolAddress((void**)&Qth, g_Qth); cudaGetSymbolAddress((void**)&Qtl, g_Qtl);
    cudaGetSymbolAddress((void**)&Vth, g_Vth); cudaGetSymbolAddress((void**)&Vtl, g_Vtl);
    cudaGetSymbolAddress((void**)&Vh,  g_Vh);  cudaGetSymbolAddress((void**)&Vl,  g_Vl);
    cudaGetSymbolAddress((void**)&Yth, g_Yth); cudaGetSymbolAddress((void**)&Ytl, g_Ytl);
    cudaGetSymbolAddress((void**)&Ph,  g_Ph);  cudaGetSymbolAddress((void**)&Pl,  g_Pl);
    cudaGetSymbolAddress((void**)&S,   g_S);

    cudaFuncSetAttribute(tgemm<0>, cudaFuncAttributeMaxDynamicSharedMemorySize, SMEMSZ);
    cudaFuncSetAttribute(tgemm<1>, cudaFuncAttributeMaxDynamicSharedMemorySize, SMEMSZ);
    cudaFuncSetAttribute(tgemm<4>, cudaFuncAttributeMaxDynamicSharedMemorySize, SMEMSZ);
    cudaFuncSetAttribute(tgemm<5>, cudaFuncAttributeMaxDynamicSharedMemorySize, SMEMSZ);

    const size_t pstr = (size_t)NDIM * CIDIM;   // Kt/Qt/Vt/Yt batch stride (elems)
    const size_t vstr = (size_t)CIDIM * NDIM;   // V batch stride
    const size_t xstr = (size_t)CDIM * NDIM;    // x/out batch stride
    const size_t tstr = (size_t)NDIM * CDIM;    // xT batch stride
    const size_t sstr = (size_t)NDIM * NDIM;    // S/P batch stride
    const size_t khStr = (size_t)BSZ * pstr;    // split-K partial stride
    float* Y0 = S;                              // reuse S as split-K partials
    float* Y1 = S + khStr;

    const int w4 = (CIDIM * CDIM) / 4;

    // 0) splits
    transpose_split<<<dim3(NDIM / 32, CDIM / 32, BSZ), dim3(32, 8)>>>(x, xTh, xTl);
    split_mat<<<(w4 + 255) / 256, 256>>>(Wk, Wkh, Wkl, w4);
    split_mat<<<(w4 + 255) / 256, 256>>>(Wq, Wqh, Wql, w4);
    split_mat<<<(w4 + 255) / 256, 256>>>(Wv, Wvh, Wvl, w4);
    split_mat<<<(w4 + 255) / 256, 256>>>(Wo, Woh, Wol, w4);

    // 1) K, Q, V projections merged (TRIPLE): {Kt,Qt,Vt}[n,d] = xT[n,:]·W[d,:] + b[d]
    tgemm<1><<<dim3(CIDIM / 128, NDIM / 128, 3 * BSZ), 256, SMEMSZ>>>(
        xTh, xTl, Wkh, Wkl, Wqh, Wql, Wvh, Wvl,
        nullptr, Kth, Ktl, Qth, Qtl, Vth, Vtl,
        CDIM, CDIM, CIDIM, tstr, 0, pstr, 0, bk, bq, bv, nullptr, 0, 1.0f);

    // 1b) V[c,n] = transpose(Vt)
    transpose_v<<<dim3(NDIM / 32, CIDIM / 32, BSZ), dim3(32, 8)>>>(Vth, Vtl, Vh, Vl);

    // 2) S[i,j] = (1/T) Kt[i,:]·Qt[j,:]  (fp32 out)
    tgemm<0><<<dim3(NDIM / 128, NDIM / 128, BSZ), 256, SMEMSZ>>>(
        Kth, Ktl, Qth, Qtl, nullptr, nullptr, nullptr, nullptr,
        S, nullptr, nullptr, nullptr, nullptr, nullptr, nullptr,
        CIDIM, CIDIM, NDIM, pstr, pstr, sstr, 0, nullptr, nullptr, nullptr,
        nullptr, 0, 1.0f / (float)TDIM);

    // 3) softmax -> P hi/lo
    softmax_split<<<BSZ * NDIM, 256>>>(S, Ph, Pl, NDIM);

    // 4) Y partials: Yp[kh][i,c] = sum_{j in half kh} P[i,j]·V[c,j]  (split-K x2)
    tgemm<5><<<dim3(CIDIM / 128, NDIM / 128, 2 * BSZ), 256, SMEMSZ>>>(
        Ph, Pl, Vh, Vl, nullptr, nullptr, nullptr, nullptr,
        Y0, nullptr, nullptr, nullptr, nullptr, nullptr, nullptr,
        NHALF, NDIM, CIDIM, sstr, vstr, pstr, khStr,
        nullptr, nullptr, nullptr, nullptr, 0, 1.0f);

    // 4b) Yt = split(Y0 + Y1)
    {
        const int n4 = (int)((size_t)BSZ * NDIM * CIDIM / 4);
        combine_split<<<(n4 + 255) / 256, 256>>>(Y0, Y1, Yth, Ytl, n4);
    }

    // 5) out[c,n] = Wo[c,:]·Yt[n,:] + bo[c] + x[c,n]  (fp32 out)
    tgemm<4><<<dim3(NDIM / 128, CDIM / 128, BSZ), 256, SMEMSZ>>>(
        Woh, Wol, Yth, Ytl, nullptr, nullptr, nullptr, nullptr,
        out, nullptr, nullptr, nullptr, nullptr, nullptr, nullptr,
        CIDIM, CIDIM, NDIM, 0, pstr, xstr, 0, bo, nullptr, nullptr, x, xstr, 1.0f);
}